// round 13
// baseline (speedup 1.0000x reference)
#include <cuda_runtime.h>
#include <cuda_fp16.h>
#include <math.h>

// Problem constants
#define SEQ   2048
#define DIM   4096
#define NH    32
#define NKV   8
#define HD    128
#define KVDIM (NKV * HD)     // 1024
#define QKVN  (DIM + 2 * KVDIM)  // 6144

typedef unsigned int u32;

// -------- scratch (device globals; no runtime allocation allowed) --------
__device__ float g_QKV[SEQ * QKVN];                    // fused QKV projection out
__device__ __half g_xh[SEQ * DIM],   g_xl[SEQ * DIM];  // split x
__device__ __half g_wh[QKVN * DIM],  g_wl[QKVN * DIM]; // wq|wk|wv transposed [N][K]
__device__ __half g_woh[DIM * DIM],  g_wol[DIM * DIM];
__device__ __half g_ah[SEQ * DIM],   g_al[SEQ * DIM];  // attention out (split)
__device__ __half g_qbh[SEQ * DIM],   g_qbl[SEQ * DIM];
__device__ __half g_kbh[SEQ * KVDIM], g_kbl[SEQ * KVDIM];
__device__ __half g_vbh[SEQ * KVDIM], g_vbl[SEQ * KVDIM];

// ============================================================================
// PTX primitives (legacy tensor path — tcgen05 not supported by this build)
// ============================================================================
__device__ __forceinline__ void ldsm4(u32* r, u32 addr) {
    asm volatile("ldmatrix.sync.aligned.m8n8.x4.shared.b16 {%0,%1,%2,%3}, [%4];\n"
        : "=r"(r[0]), "=r"(r[1]), "=r"(r[2]), "=r"(r[3]) : "r"(addr));
}
__device__ __forceinline__ void ldsm4t(u32* r, u32 addr) {
    asm volatile("ldmatrix.sync.aligned.m8n8.x4.trans.shared.b16 {%0,%1,%2,%3}, [%4];\n"
        : "=r"(r[0]), "=r"(r[1]), "=r"(r[2]), "=r"(r[3]) : "r"(addr));
}
__device__ __forceinline__ void mma16816(float* c, const u32* a, const u32* b) {
    asm volatile("mma.sync.aligned.m16n8k16.row.col.f32.f16.f16.f32 "
        "{%0,%1,%2,%3}, {%4,%5,%6,%7}, {%8,%9}, {%0,%1,%2,%3};\n"
        : "+f"(c[0]), "+f"(c[1]), "+f"(c[2]), "+f"(c[3])
        : "r"(a[0]), "r"(a[1]), "r"(a[2]), "r"(a[3]), "r"(b[0]), "r"(b[1]));
}
__device__ __forceinline__ void cp16(u32 dst, const void* src) {
    asm volatile("cp.async.cg.shared.global [%0], [%1], 16;\n" :: "r"(dst), "l"(src));
}

// ============================================================================
// Split fp32 -> fp16 hi + fp16 lo(residual). Vectorized x4.
// ============================================================================
__global__ void split_kernel(const float* __restrict__ in,
                             __half* __restrict__ hi,
                             __half* __restrict__ lo, int n4)
{
    int i = blockIdx.x * blockDim.x + threadIdx.x;
    if (i >= n4) return;
    float4 v = ((const float4*)in)[i];
    __half2 h01 = __floats2half2_rn(v.x, v.y);
    __half2 h23 = __floats2half2_rn(v.z, v.w);
    __half2 l01 = __floats2half2_rn(v.x - __half2float(__low2half(h01)),
                                    v.y - __half2float(__high2half(h01)));
    __half2 l23 = __floats2half2_rn(v.z - __half2float(__low2half(h23)),
                                    v.w - __half2float(__high2half(h23)));
    ((__half2*)hi)[2 * i]     = h01;
    ((__half2*)hi)[2 * i + 1] = h23;
    ((__half2*)lo)[2 * i]     = l01;
    ((__half2*)lo)[2 * i + 1] = l23;
}

// ============================================================================
// Transpose + split: in fp32 [K][N] -> hi/lo fp16 [N][K].
// ============================================================================
__global__ void transpose_split_kernel(const float* __restrict__ in,
                                       __half* __restrict__ hi,
                                       __half* __restrict__ lo,
                                       int K, int N)
{
    __shared__ float t[32][33];
    int n0 = blockIdx.x * 32, k0 = blockIdx.y * 32;
    int tx = threadIdx.x, ty = threadIdx.y;   // (32, 8)
    #pragma unroll
    for (int i = 0; i < 4; i++)
        t[ty + i * 8][tx] = in[(size_t)(k0 + ty + i * 8) * N + n0 + tx];
    __syncthreads();
    #pragma unroll
    for (int i = 0; i < 4; i++) {
        float v = t[tx][ty + i * 8];
        __half h = __float2half_rn(v);
        size_t o = (size_t)(n0 + ty + i * 8) * K + k0 + tx;
        hi[o] = h;
        lo[o] = __float2half_rn(v - __half2float(h));
    }
}

// ============================================================================
// fp16x3-split tensor-core GEMM: C[M,N] fp32 = A @ B^T
//   A: hi/lo fp16 [M][K];  B: hi/lo fp16 [N][K] (K-major)
// 128x128x64 tiles, 256 threads (8 warps, 4m x 2n), mma.sync.m16n8k16,
// 2-stage cp.async pipeline (one sync pair per 64-deep k-slab).
// ============================================================================
#define GBK   64
#define GLD   72                 // padded row stride in halfs (144B; 144%128==16 -> conflict-free)
#define GTILE (128 * GLD)        // halfs per tile buffer
#define GTILEB (GTILE * 2)       // 18432 bytes
#define GSMEM (8 * GTILEB)       // 4 matrices x 2 stages = 147456 B

__global__ __launch_bounds__(256) void gemm_fp16x3(
    const __half* __restrict__ Ah, const __half* __restrict__ Al,
    const __half* __restrict__ Bh, const __half* __restrict__ Bl,
    float* __restrict__ C, int M, int N, int K)
{
    extern __shared__ __half smg[];
    __half* sAh = smg;
    __half* sAl = sAh + 2 * GTILE;
    __half* sBh = sAl + 2 * GTILE;
    __half* sBl = sBh + 2 * GTILE;

    const int tid  = threadIdx.x;
    const int lane = tid & 31;
    const int warp = tid >> 5;
    const int wm   = warp & 3;    // 0..3 -> 32-row slab
    const int wn   = warp >> 2;   // 0..1 -> 64-col slab
    const int m0   = blockIdx.y * 128;
    const int n0   = blockIdx.x * 128;

    const u32 sAh0 = (u32)__cvta_generic_to_shared(sAh);
    const u32 sAl0 = (u32)__cvta_generic_to_shared(sAl);
    const u32 sBh0 = (u32)__cvta_generic_to_shared(sBh);
    const u32 sBl0 = (u32)__cvta_generic_to_shared(sBl);

    // loader: row = tid>>1 (0..127), half-row = (tid&1)*32 halfs (64B = 4 chunks)
    const int lrow = tid >> 1;
    const int lkc  = (tid & 1) * 32;
    const size_t gA = (size_t)(m0 + lrow) * K + lkc;
    const size_t gB = (size_t)(n0 + lrow) * K + lkc;
    const u32 sOff  = (u32)(lrow * GLD + lkc) * 2;

    float acc[2][8][4];
    #pragma unroll
    for (int a = 0; a < 2; a++)
        #pragma unroll
        for (int b = 0; b < 8; b++)
            #pragma unroll
            for (int c = 0; c < 4; c++) acc[a][b][c] = 0.f;

    // ldmatrix fragment byte offsets within a stage
    const u32 aOff = (u32)((wm * 32 + (lane & 15)) * GLD) * 2 + (lane >> 4) * 16;
    const u32 bOff = (u32)((wn * 64 + (lane & 7) + ((lane >> 4) & 1) * 8) * GLD) * 2
                   + ((lane >> 3) & 1) * 16;

    const int nk = K / GBK;

    // stage fill (4 x 16B chunks per tile per thread)
    auto fill = [&](int s, int kt) {
        const u32 sb = (u32)(s * GTILEB);
        const int kk = kt * GBK;
        #pragma unroll
        for (int c = 0; c < 4; c++) {
            cp16(sAh0 + sb + sOff + c * 16, Ah + gA + kk + c * 8);
            cp16(sAl0 + sb + sOff + c * 16, Al + gA + kk + c * 8);
            cp16(sBh0 + sb + sOff + c * 16, Bh + gB + kk + c * 8);
            cp16(sBl0 + sb + sOff + c * 16, Bl + gB + kk + c * 8);
        }
        asm volatile("cp.async.commit_group;\n");
    };

    fill(0, 0);
    if (nk > 1) fill(1, 1);

    for (int it = 0; it < nk; it++) {
        if (it + 1 < nk) asm volatile("cp.async.wait_group 1;\n" ::: "memory");
        else             asm volatile("cp.async.wait_group 0;\n" ::: "memory");
        __syncthreads();

        const u32 sb = (u32)((it & 1) * GTILEB);
        #pragma unroll
        for (int ks = 0; ks < 4; ks++) {
            const u32 kb = sb + ks * 32;    // k16 step = 32 bytes
            u32 a_hi[2][4], a_lo[2][4], b_hi[4][4], b_lo[4][4];
            #pragma unroll
            for (int mt = 0; mt < 2; mt++) {
                ldsm4(a_hi[mt], sAh0 + kb + aOff + mt * (16 * GLD * 2));
                ldsm4(a_lo[mt], sAl0 + kb + aOff + mt * (16 * GLD * 2));
            }
            #pragma unroll
            for (int np = 0; np < 4; np++) {
                ldsm4(b_hi[np], sBh0 + kb + bOff + np * (16 * GLD * 2));
                ldsm4(b_lo[np], sBl0 + kb + bOff + np * (16 * GLD * 2));
            }
            #pragma unroll
            for (int mt = 0; mt < 2; mt++)
                #pragma unroll
                for (int nt = 0; nt < 8; nt++) {
                    const u32* bh = &b_hi[nt >> 1][(nt & 1) * 2];
                    const u32* bl = &b_lo[nt >> 1][(nt & 1) * 2];
                    mma16816(acc[mt][nt], a_hi[mt], bh);
                    mma16816(acc[mt][nt], a_lo[mt], bh);
                    mma16816(acc[mt][nt], a_hi[mt], bl);
                }
        }
        __syncthreads();
        if (it + 2 < nk) fill(it & 1, it + 2);
    }

    // epilogue: fragment -> fp32 global
    const int erow = m0 + wm * 32 + (lane >> 2);
    const int ecol = n0 + wn * 64 + (lane & 3) * 2;
    #pragma unroll
    for (int mt = 0; mt < 2; mt++)
        #pragma unroll
        for (int nt = 0; nt < 8; nt++) {
            int r = erow + mt * 16;
            int c = ecol + nt * 8;
            *(float2*)&C[(size_t)r * N + c] =
                make_float2(acc[mt][nt][0], acc[mt][nt][1]);
            *(float2*)&C[(size_t)(r + 8) * N + c] =
                make_float2(acc[mt][nt][2], acc[mt][nt][3]);
        }
}

// ============================================================================
// RoPE + fp16 hi/lo split, reading from the fused QKV buffer (strided).
// ============================================================================
__global__ void rope_split_kernel(const float* __restrict__ src, int srcStride,
                                  int colOff,
                                  __half* __restrict__ hi,
                                  __half* __restrict__ lo,
                                  int n_heads, float scale)
{
    int idx = blockIdx.x * blockDim.x + threadIdx.x;
    int total = SEQ * n_heads * (HD / 2);
    if (idx >= total) return;
    int i   = idx & 63;
    int h   = (idx >> 6) % n_heads;
    int pos = idx / (64 * n_heads);

    float inv = powf(10000.0f, -(float)(2 * i) / 128.0f);
    float ang = (float)pos * inv;
    float s, c;
    sincosf(ang, &s, &c);

    const float* p = src + (size_t)pos * srcStride + colOff + h * HD + 2 * i;
    float a = p[0], b = p[1];
    float o0 = (a * c - b * s) * scale;
    float o1 = (a * s + b * c) * scale;

    size_t off = ((size_t)pos * n_heads + h) * HD + 2 * i;
    __half2 hh = __floats2half2_rn(o0, o1);
    __half2 ll = __floats2half2_rn(o0 - __half2float(__low2half(hh)),
                                   o1 - __half2float(__high2half(hh)));
    ((__half2*)hi)[off >> 1] = hh;
    ((__half2*)lo)[off >> 1] = ll;
}

// ============================================================================
// Strided split (V slice of fused QKV buffer) -> contiguous fp16 hi/lo.
// ============================================================================
__global__ void vsplit_kernel(const float* __restrict__ src, int srcStride,
                              int colOff,
                              __half* __restrict__ hi,
                              __half* __restrict__ lo, int n4)
{
    int idx = blockIdx.x * blockDim.x + threadIdx.x;
    if (idx >= n4) return;
    int row = idx / (KVDIM / 4);
    int c4  = idx % (KVDIM / 4);
    float4 v = *(const float4*)(src + (size_t)row * srcStride + colOff + c4 * 4);
    __half2 h01 = __floats2half2_rn(v.x, v.y);
    __half2 h23 = __floats2half2_rn(v.z, v.w);
    __half2 l01 = __floats2half2_rn(v.x - __half2float(__low2half(h01)),
                                    v.y - __half2float(__high2half(h01)));
    __half2 l23 = __floats2half2_rn(v.z - __half2float(__low2half(h23)),
                                    v.w - __half2float(__high2half(h23)));
    size_t o = (size_t)row * (KVDIM / 2) + c4 * 2;
    ((__half2*)hi)[o]     = h01;
    ((__half2*)hi)[o + 1] = h23;
    ((__half2*)lo)[o]     = l01;
    ((__half2*)lo)[o + 1] = l23;
}

// ============================================================================
// Tensor-core flash attention (causal, GQA), fp16x3-split.
// grid = (SEQ/64, NH), 128 threads; qb order reversed (longest CTAs first).
// Epilogue writes the fp16 hi/lo split of O directly (feeds the wo GEMM).
// ============================================================================
#define LDB   136
#define ATILE (64 * LDB)
#define ASMEM (6 * ATILE * 2)    // 104448 B -> 2 CTAs/SM

__global__ __launch_bounds__(128) void attn_mma(
    const __half* __restrict__ Qh, const __half* __restrict__ Ql,
    const __half* __restrict__ Kh, const __half* __restrict__ Kl,
    const __half* __restrict__ Vh, const __half* __restrict__ Vl,
    __half* __restrict__ Oh, __half* __restrict__ Ol)
{
    extern __shared__ __half sma[];
    const u32 sQh = (u32)__cvta_generic_to_shared(sma);
    const u32 sQl = sQh + ATILE * 2;
    const u32 sKh = sQl + ATILE * 2;
    const u32 sKl = sKh + ATILE * 2;
    const u32 sVh = sKl + ATILE * 2;
    const u32 sVl = sVh + ATILE * 2;

    const int tid  = threadIdx.x;
    const int lane = tid & 31;
    const int warp = tid >> 5;
    const int qb   = gridDim.x - 1 - blockIdx.x;   // longest blocks first
    const int h    = blockIdx.y;
    const int kvh  = h >> 2;
    const int g    = lane >> 2;
    const int tig  = lane & 3;

    const int lrow  = tid >> 1;
    const int lhalf = (tid & 1) * 64;
    const u32 sOff  = (u32)(lrow * LDB + lhalf) * 2;

    {
        size_t qo = ((size_t)(qb * 64 + lrow) * NH + h) * HD + lhalf;
        #pragma unroll
        for (int c = 0; c < 8; c++) {
            cp16(sQh + sOff + c * 16, Qh + qo + c * 8);
            cp16(sQl + sOff + c * 16, Ql + qo + c * 8);
        }
        asm volatile("cp.async.commit_group;\n");
    }

    const u32 aO = (u32)((warp * 16 + (lane & 15)) * LDB) * 2 + (lane >> 4) * 16;
    const u32 bO = (u32)(((lane & 7) + ((lane >> 4) & 1) * 8) * LDB) * 2
                 + ((lane >> 3) & 1) * 16;
    const u32 vO = (u32)((lane & 15) * LDB) * 2 + (lane >> 4) * 16;

    float m[2] = {-1e30f, -1e30f}, l[2] = {0.f, 0.f};
    float acc[16][4];
    #pragma unroll
    for (int nt = 0; nt < 16; nt++)
        #pragma unroll
        for (int c = 0; c < 4; c++) acc[nt][c] = 0.f;

    for (int j = 0; j <= qb; j++) {
        __syncthreads();
        {
            size_t ko = ((size_t)(j * 64 + lrow) * NKV + kvh) * HD + lhalf;
            #pragma unroll
            for (int c = 0; c < 8; c++) {
                cp16(sKh + sOff + c * 16, Kh + ko + c * 8);
                cp16(sKl + sOff + c * 16, Kl + ko + c * 8);
                cp16(sVh + sOff + c * 16, Vh + ko + c * 8);
                cp16(sVl + sOff + c * 16, Vl + ko + c * 8);
            }
            asm volatile("cp.async.commit_group;\n");
            asm volatile("cp.async.wait_group 0;\n");
        }
        __syncthreads();

        float sv[8][4];
        #pragma unroll
        for (int nt = 0; nt < 8; nt++)
            #pragma unroll
            for (int c = 0; c < 4; c++) sv[nt][c] = 0.f;

        #pragma unroll
        for (int ks = 0; ks < 8; ks++) {
            const u32 kb = ks * 32;
            u32 ah[4], al[4];
            ldsm4(ah, sQh + aO + kb);
            ldsm4(al, sQl + aO + kb);
            #pragma unroll
            for (int np = 0; np < 4; np++) {
                u32 bh[4], bl[4];
                ldsm4(bh, sKh + bO + np * (16 * LDB * 2) + kb);
                ldsm4(bl, sKl + bO + np * (16 * LDB * 2) + kb);
                mma16816(sv[2 * np],     ah, &bh[0]);
                mma16816(sv[2 * np],     al, &bh[0]);
                mma16816(sv[2 * np],     ah, &bl[0]);
                mma16816(sv[2 * np + 1], ah, &bh[2]);
                mma16816(sv[2 * np + 1], al, &bh[2]);
                mma16816(sv[2 * np + 1], ah, &bl[2]);
            }
        }

        if (j == qb) {
            #pragma unroll
            for (int nt = 0; nt < 8; nt++)
                #pragma unroll
                for (int c = 0; c < 4; c++) {
                    int col = nt * 8 + tig * 2 + (c & 1);
                    int row = warp * 16 + g + (c >> 1) * 8;
                    if (col > row) sv[nt][c] = -1e30f;
                }
        }

        #pragma unroll
        for (int half = 0; half < 2; half++) {
            float rm = -1e30f;
            #pragma unroll
            for (int nt = 0; nt < 8; nt++)
                rm = fmaxf(rm, fmaxf(sv[nt][half * 2], sv[nt][half * 2 + 1]));
            rm = fmaxf(rm, __shfl_xor_sync(0xffffffffu, rm, 1));
            rm = fmaxf(rm, __shfl_xor_sync(0xffffffffu, rm, 2));
            float mn   = fmaxf(m[half], rm);
            float corr = __expf(m[half] - mn);
            float rs = 0.f;
            #pragma unroll
            for (int nt = 0; nt < 8; nt++) {
                float p0 = __expf(sv[nt][half * 2]     - mn);
                float p1 = __expf(sv[nt][half * 2 + 1] - mn);
                sv[nt][half * 2]     = p0;
                sv[nt][half * 2 + 1] = p1;
                rs += p0 + p1;
            }
            rs += __shfl_xor_sync(0xffffffffu, rs, 1);
            rs += __shfl_xor_sync(0xffffffffu, rs, 2);
            l[half] = l[half] * corr + rs;
            m[half] = mn;
            #pragma unroll
            for (int nt = 0; nt < 16; nt++) {
                acc[nt][half * 2]     *= corr;
                acc[nt][half * 2 + 1] *= corr;
            }
        }
        __syncwarp();

        #pragma unroll
        for (int ks = 0; ks < 4; ks++) {
            u32 pa_h[4], pa_l[4];
            #pragma unroll
            for (int t = 0; t < 2; t++) {
                float p0 = sv[2 * ks + t][0], p1 = sv[2 * ks + t][1];
                float p2 = sv[2 * ks + t][2], p3 = sv[2 * ks + t][3];
                __half2 h01 = __floats2half2_rn(p0, p1);
                __half2 h23 = __floats2half2_rn(p2, p3);
                __half2 l01 = __floats2half2_rn(p0 - __half2float(__low2half(h01)),
                                                p1 - __half2float(__high2half(h01)));
                __half2 l23 = __floats2half2_rn(p2 - __half2float(__low2half(h23)),
                                                p3 - __half2float(__high2half(h23)));
                pa_h[2 * t]     = *(u32*)&h01;
                pa_h[2 * t + 1] = *(u32*)&h23;
                pa_l[2 * t]     = *(u32*)&l01;
                pa_l[2 * t + 1] = *(u32*)&l23;
            }
            const u32 kb = (u32)(ks * 16 * LDB) * 2;
            #pragma unroll
            for (int np = 0; np < 8; np++) {
                u32 vh[4], vl[4];
                ldsm4t(vh, sVh + vO + kb + np * 32);
                ldsm4t(vl, sVl + vO + kb + np * 32);
                mma16816(acc[2 * np],     pa_h, &vh[0]);
                mma16816(acc[2 * np],     pa_l, &vh[0]);
                mma16816(acc[2 * np],     pa_h, &vl[0]);
                mma16816(acc[2 * np + 1], pa_h, &vh[2]);
                mma16816(acc[2 * np + 1], pa_l, &vh[2]);
                mma16816(acc[2 * np + 1], pa_h, &vl[2]);
            }
        }
    }

    // ---- epilogue: normalize + fp16 hi/lo split, write directly ----
    #pragma unroll
    for (int half = 0; half < 2; half++) {
        float inv = 1.0f / l[half];
        int row = qb * 64 + warp * 16 + g + half * 8;
        size_t base = (size_t)row * DIM + h * HD;
        #pragma unroll
        for (int nt = 0; nt < 16; nt++) {
            int col = nt * 8 + tig * 2;
            float v0 = acc[nt][half * 2] * inv;
            float v1 = acc[nt][half * 2 + 1] * inv;
            __half2 hh = __floats2half2_rn(v0, v1);
            __half2 ll = __floats2half2_rn(v0 - __half2float(__low2half(hh)),
                                           v1 - __half2float(__high2half(hh)));
            *(__half2*)(Oh + base + col) = hh;
            *(__half2*)(Ol + base + col) = ll;
        }
    }
}

// ============================================================================
// kernel_launch
// ============================================================================
extern "C" void kernel_launch(void* const* d_in, const int* in_sizes, int n_in,
                              void* d_out, int out_size)
{
    const float* x  = (const float*)d_in[0];
    const float* wq = (const float*)d_in[1];
    const float* wk = (const float*)d_in[2];
    const float* wv = (const float*)d_in[3];
    const float* wo = (const float*)d_in[4];
    float* out = (float*)d_out;

    float* QKV;
    cudaGetSymbolAddress((void**)&QKV, g_QKV);
    __half *xh, *xl, *wh, *wl, *woh, *wol, *ah, *al;
    __half *qbh, *qbl, *kbh, *kbl, *vbh, *vbl;
    cudaGetSymbolAddress((void**)&xh,  g_xh);  cudaGetSymbolAddress((void**)&xl,  g_xl);
    cudaGetSymbolAddress((void**)&wh,  g_wh);  cudaGetSymbolAddress((void**)&wl,  g_wl);
    cudaGetSymbolAddress((void**)&woh, g_woh); cudaGetSymbolAddress((void**)&wol, g_wol);
    cudaGetSymbolAddress((void**)&ah,  g_ah);  cudaGetSymbolAddress((void**)&al,  g_al);
    cudaGetSymbolAddress((void**)&qbh, g_qbh); cudaGetSymbolAddress((void**)&qbl, g_qbl);
    cudaGetSymbolAddress((void**)&kbh, g_kbh); cudaGetSymbolAddress((void**)&kbl, g_kbl);
    cudaGetSymbolAddress((void**)&vbh, g_vbh); cudaGetSymbolAddress((void**)&vbl, g_vbl);

    cudaFuncSetAttribute(gemm_fp16x3,
                         cudaFuncAttributeMaxDynamicSharedMemorySize, GSMEM);
    cudaFuncSetAttribute(attn_mma,
                         cudaFuncAttributeMaxDynamicSharedMemorySize, ASMEM);

    // 1) split x; transpose+split weights into the fused [6144][4096] buffer
    split_kernel<<<(SEQ * DIM / 4 + 255) / 256, 256>>>(x, xh, xl, SEQ * DIM / 4);
    transpose_split_kernel<<<dim3(DIM   / 32, DIM / 32), dim3(32, 8)>>>(
        wq, wh, wl, DIM, DIM);
    transpose_split_kernel<<<dim3(KVDIM / 32, DIM / 32), dim3(32, 8)>>>(
        wk, wh + (size_t)DIM * DIM, wl + (size_t)DIM * DIM, DIM, KVDIM);
    transpose_split_kernel<<<dim3(KVDIM / 32, DIM / 32), dim3(32, 8)>>>(
        wv, wh + (size_t)(DIM + KVDIM) * DIM, wl + (size_t)(DIM + KVDIM) * DIM, DIM, KVDIM);
    transpose_split_kernel<<<dim3(DIM   / 32, DIM / 32), dim3(32, 8)>>>(
        wo, woh, wol, DIM, DIM);

    // 2) fused QKV projection (one GEMM: N = 6144)
    gemm_fp16x3<<<dim3(QKVN / 128, SEQ / 128), 256, GSMEM>>>(
        xh, xl, wh, wl, QKV, SEQ, QKVN, DIM);

    // 3) RoPE + fp16 split (fold 1/sqrt(HD) into Q); strided split for V
    const float scale = 0.08838834764831845f;
    int nq = SEQ * NH  * (HD / 2);
    int nk = SEQ * NKV * (HD / 2);
    rope_split_kernel<<<(nq + 255) / 256, 256>>>(QKV, QKVN, 0,    qbh, qbl, NH,  scale);
    rope_split_kernel<<<(nk + 255) / 256, 256>>>(QKV, QKVN, DIM,  kbh, kbl, NKV, 1.0f);
    vsplit_kernel<<<(SEQ * KVDIM / 4 + 255) / 256, 256>>>(
        QKV, QKVN, DIM + KVDIM, vbh, vbl, SEQ * KVDIM / 4);

    // 4) tensor-core attention (epilogue writes split O directly)
    attn_mma<<<dim3(SEQ / 64, NH), 128, ASMEM>>>(qbh, qbl, kbh, kbl, vbh, vbl, ah, al);

    // 5) output projection
    gemm_fp16x3<<<dim3(DIM / 128, SEQ / 128), 256, GSMEM>>>(
        ah, al, woh, wol, out, SEQ, DIM, DIM);
}

// round 14
// speedup vs baseline: 1.2661x; 1.2661x over previous
#include <cuda_runtime.h>
#include <cuda_fp16.h>
#include <math.h>

// Problem constants
#define SEQ   2048
#define DIM   4096
#define NH    32
#define NKV   8
#define HD    128
#define KVDIM (NKV * HD)     // 1024
#define QKVN  (DIM + 2 * KVDIM)  // 6144

typedef unsigned int u32;

// -------- scratch (device globals; no runtime allocation allowed) --------
__device__ float g_QKV[SEQ * QKVN];                    // fused QKV projection out
__device__ __half g_xh[SEQ * DIM],   g_xl[SEQ * DIM];  // split x
__device__ __half g_wh[QKVN * DIM],  g_wl[QKVN * DIM]; // wq|wk|wv transposed [N][K]
__device__ __half g_woh[DIM * DIM],  g_wol[DIM * DIM];
__device__ __half g_ah[SEQ * DIM],   g_al[SEQ * DIM];  // attention out (split)
__device__ __half g_qbh[SEQ * DIM],   g_qbl[SEQ * DIM];
__device__ __half g_kbh[SEQ * KVDIM], g_kbl[SEQ * KVDIM];
__device__ __half g_vbh[SEQ * KVDIM], g_vbl[SEQ * KVDIM];

// ============================================================================
// PTX primitives (legacy tensor path — tcgen05 not supported by this build)
// ============================================================================
__device__ __forceinline__ void ldsm4(u32* r, u32 addr) {
    asm volatile("ldmatrix.sync.aligned.m8n8.x4.shared.b16 {%0,%1,%2,%3}, [%4];\n"
        : "=r"(r[0]), "=r"(r[1]), "=r"(r[2]), "=r"(r[3]) : "r"(addr));
}
__device__ __forceinline__ void ldsm4t(u32* r, u32 addr) {
    asm volatile("ldmatrix.sync.aligned.m8n8.x4.trans.shared.b16 {%0,%1,%2,%3}, [%4];\n"
        : "=r"(r[0]), "=r"(r[1]), "=r"(r[2]), "=r"(r[3]) : "r"(addr));
}
__device__ __forceinline__ void mma16816(float* c, const u32* a, const u32* b) {
    asm volatile("mma.sync.aligned.m16n8k16.row.col.f32.f16.f16.f32 "
        "{%0,%1,%2,%3}, {%4,%5,%6,%7}, {%8,%9}, {%0,%1,%2,%3};\n"
        : "+f"(c[0]), "+f"(c[1]), "+f"(c[2]), "+f"(c[3])
        : "r"(a[0]), "r"(a[1]), "r"(a[2]), "r"(a[3]), "r"(b[0]), "r"(b[1]));
}
__device__ __forceinline__ void cp16(u32 dst, const void* src) {
    asm volatile("cp.async.cg.shared.global [%0], [%1], 16;\n" :: "r"(dst), "l"(src));
}

// ============================================================================
// Split fp32 -> fp16 hi + fp16 lo(residual). Vectorized x4.
// ============================================================================
__global__ void split_kernel(const float* __restrict__ in,
                             __half* __restrict__ hi,
                             __half* __restrict__ lo, int n4)
{
    int i = blockIdx.x * blockDim.x + threadIdx.x;
    if (i >= n4) return;
    float4 v = ((const float4*)in)[i];
    __half2 h01 = __floats2half2_rn(v.x, v.y);
    __half2 h23 = __floats2half2_rn(v.z, v.w);
    __half2 l01 = __floats2half2_rn(v.x - __half2float(__low2half(h01)),
                                    v.y - __half2float(__high2half(h01)));
    __half2 l23 = __floats2half2_rn(v.z - __half2float(__low2half(h23)),
                                    v.w - __half2float(__high2half(h23)));
    ((__half2*)hi)[2 * i]     = h01;
    ((__half2*)hi)[2 * i + 1] = h23;
    ((__half2*)lo)[2 * i]     = l01;
    ((__half2*)lo)[2 * i + 1] = l23;
}

// ============================================================================
// Transpose + split: in fp32 [K][N] -> hi/lo fp16 [N][K].
// ============================================================================
__global__ void transpose_split_kernel(const float* __restrict__ in,
                                       __half* __restrict__ hi,
                                       __half* __restrict__ lo,
                                       int K, int N)
{
    __shared__ float t[32][33];
    int n0 = blockIdx.x * 32, k0 = blockIdx.y * 32;
    int tx = threadIdx.x, ty = threadIdx.y;   // (32, 8)
    #pragma unroll
    for (int i = 0; i < 4; i++)
        t[ty + i * 8][tx] = in[(size_t)(k0 + ty + i * 8) * N + n0 + tx];
    __syncthreads();
    #pragma unroll
    for (int i = 0; i < 4; i++) {
        float v = t[tx][ty + i * 8];
        __half h = __float2half_rn(v);
        size_t o = (size_t)(n0 + ty + i * 8) * K + k0 + tx;
        hi[o] = h;
        lo[o] = __float2half_rn(v - __half2float(h));
    }
}

// ============================================================================
// fp16x3-split tensor-core GEMM: C[M,N] fp32 = A @ B^T
//   A: hi/lo fp16 [M][K];  B: hi/lo fp16 [N][K] (K-major)
// 128x128x32 tiles, 256 threads (8 warps, 4m x 2n), mma.sync.m16n8k16,
// cp.async double-buffered (R11-measured config: 81,920 B smem -> 2 CTAs/SM,
// prefetch issued BEFORE the wait on the current stage).
// ============================================================================
#define GBK   32
#define GLD   40                 // padded row stride in halfs
#define GTILE (128 * GLD)        // halfs per tile buffer
#define GTILEB (GTILE * 2)       // 10240 bytes
#define GSMEM (8 * GTILEB)       // 4 matrices x 2 stages = 81920 B

__global__ __launch_bounds__(256) void gemm_fp16x3(
    const __half* __restrict__ Ah, const __half* __restrict__ Al,
    const __half* __restrict__ Bh, const __half* __restrict__ Bl,
    float* __restrict__ C, int M, int N, int K)
{
    extern __shared__ __half smg[];
    __half* sAh = smg;
    __half* sAl = sAh + 2 * GTILE;
    __half* sBh = sAl + 2 * GTILE;
    __half* sBl = sBh + 2 * GTILE;

    const int tid  = threadIdx.x;
    const int lane = tid & 31;
    const int warp = tid >> 5;
    const int wm   = warp & 3;    // 0..3 -> 32-row slab
    const int wn   = warp >> 2;   // 0..1 -> 64-col slab
    const int m0   = blockIdx.y * 128;
    const int n0   = blockIdx.x * 128;

    const u32 sAh0 = (u32)__cvta_generic_to_shared(sAh);
    const u32 sAl0 = (u32)__cvta_generic_to_shared(sAl);
    const u32 sBh0 = (u32)__cvta_generic_to_shared(sBh);
    const u32 sBl0 = (u32)__cvta_generic_to_shared(sBl);

    // loader: 2 x 16B per tile per thread (rows r, r+64)
    const int lrow = tid >> 2;            // 0..63
    const int lkc  = (tid & 3) * 8;       // half col 0,8,16,24
    const size_t gA = (size_t)(m0 + lrow) * K + lkc;
    const size_t gB = (size_t)(n0 + lrow) * K + lkc;
    const u32 sOff  = (u32)(lrow * GLD + lkc) * 2;
    const u32 sOff2 = sOff + 64 * GLD * 2;

    float acc[2][8][4];
    #pragma unroll
    for (int a = 0; a < 2; a++)
        #pragma unroll
        for (int b = 0; b < 8; b++)
            #pragma unroll
            for (int c = 0; c < 4; c++) acc[a][b][c] = 0.f;

    // ldmatrix fragment byte offsets within a stage
    const u32 aOff = (u32)((wm * 32 + (lane & 15)) * GLD + (lane >> 4) * 8) * 2;
    const u32 bOff = (u32)((wn * 64 + (lane & 7) + ((lane >> 4) & 1) * 8) * GLD
                           + ((lane >> 3) & 1) * 8) * 2;

    const int nk = K / GBK;

    // prologue: stage 0
    {
        cp16(sAh0 + sOff,  Ah + gA);  cp16(sAh0 + sOff2, Ah + gA + (size_t)64 * K);
        cp16(sAl0 + sOff,  Al + gA);  cp16(sAl0 + sOff2, Al + gA + (size_t)64 * K);
        cp16(sBh0 + sOff,  Bh + gB);  cp16(sBh0 + sOff2, Bh + gB + (size_t)64 * K);
        cp16(sBl0 + sOff,  Bl + gB);  cp16(sBl0 + sOff2, Bl + gB + (size_t)64 * K);
        asm volatile("cp.async.commit_group;\n");
    }

    for (int it = 0; it < nk; it++) {
        if (it + 1 < nk) {
            const int kk = (it + 1) * GBK;
            const u32 sb = (u32)(((it + 1) & 1) * GTILEB);
            cp16(sAh0 + sb + sOff,  Ah + gA + kk);
            cp16(sAh0 + sb + sOff2, Ah + gA + kk + (size_t)64 * K);
            cp16(sAl0 + sb + sOff,  Al + gA + kk);
            cp16(sAl0 + sb + sOff2, Al + gA + kk + (size_t)64 * K);
            cp16(sBh0 + sb + sOff,  Bh + gB + kk);
            cp16(sBh0 + sb + sOff2, Bh + gB + kk + (size_t)64 * K);
            cp16(sBl0 + sb + sOff,  Bl + gB + kk);
            cp16(sBl0 + sb + sOff2, Bl + gB + kk + (size_t)64 * K);
            asm volatile("cp.async.commit_group;\n");
            asm volatile("cp.async.wait_group 1;\n");
        } else {
            asm volatile("cp.async.wait_group 0;\n");
        }
        __syncthreads();

        const u32 sb = (u32)((it & 1) * GTILEB);
        #pragma unroll
        for (int ks = 0; ks < 2; ks++) {
            const u32 kb = sb + ks * 32;    // k16 step = 32 bytes
            u32 a_hi[2][4], a_lo[2][4], b_hi[4][4], b_lo[4][4];
            #pragma unroll
            for (int mt = 0; mt < 2; mt++) {
                ldsm4(a_hi[mt], sAh0 + kb + aOff + mt * (16 * GLD * 2));
                ldsm4(a_lo[mt], sAl0 + kb + aOff + mt * (16 * GLD * 2));
            }
            #pragma unroll
            for (int np = 0; np < 4; np++) {
                ldsm4(b_hi[np], sBh0 + kb + bOff + np * (16 * GLD * 2));
                ldsm4(b_lo[np], sBl0 + kb + bOff + np * (16 * GLD * 2));
            }
            #pragma unroll
            for (int mt = 0; mt < 2; mt++)
                #pragma unroll
                for (int nt = 0; nt < 8; nt++) {
                    const u32* bh = &b_hi[nt >> 1][(nt & 1) * 2];
                    const u32* bl = &b_lo[nt >> 1][(nt & 1) * 2];
                    mma16816(acc[mt][nt], a_hi[mt], bh);
                    mma16816(acc[mt][nt], a_lo[mt], bh);
                    mma16816(acc[mt][nt], a_hi[mt], bl);
                }
        }
        __syncthreads();
    }

    // epilogue: fragment -> fp32 global
    const int erow = m0 + wm * 32 + (lane >> 2);
    const int ecol = n0 + wn * 64 + (lane & 3) * 2;
    #pragma unroll
    for (int mt = 0; mt < 2; mt++)
        #pragma unroll
        for (int nt = 0; nt < 8; nt++) {
            int r = erow + mt * 16;
            int c = ecol + nt * 8;
            *(float2*)&C[(size_t)r * N + c] =
                make_float2(acc[mt][nt][0], acc[mt][nt][1]);
            *(float2*)&C[(size_t)(r + 8) * N + c] =
                make_float2(acc[mt][nt][2], acc[mt][nt][3]);
        }
}

// ============================================================================
// RoPE + fp16 hi/lo split, reading from the fused QKV buffer (strided).
// ============================================================================
__global__ void rope_split_kernel(const float* __restrict__ src, int srcStride,
                                  int colOff,
                                  __half* __restrict__ hi,
                                  __half* __restrict__ lo,
                                  int n_heads, float scale)
{
    int idx = blockIdx.x * blockDim.x + threadIdx.x;
    int total = SEQ * n_heads * (HD / 2);
    if (idx >= total) return;
    int i   = idx & 63;
    int h   = (idx >> 6) % n_heads;
    int pos = idx / (64 * n_heads);

    float inv = powf(10000.0f, -(float)(2 * i) / 128.0f);
    float ang = (float)pos * inv;
    float s, c;
    sincosf(ang, &s, &c);

    const float* p = src + (size_t)pos * srcStride + colOff + h * HD + 2 * i;
    float a = p[0], b = p[1];
    float o0 = (a * c - b * s) * scale;
    float o1 = (a * s + b * c) * scale;

    size_t off = ((size_t)pos * n_heads + h) * HD + 2 * i;
    __half2 hh = __floats2half2_rn(o0, o1);
    __half2 ll = __floats2half2_rn(o0 - __half2float(__low2half(hh)),
                                   o1 - __half2float(__high2half(hh)));
    ((__half2*)hi)[off >> 1] = hh;
    ((__half2*)lo)[off >> 1] = ll;
}

// ============================================================================
// Strided split (V slice of fused QKV buffer) -> contiguous fp16 hi/lo.
// ============================================================================
__global__ void vsplit_kernel(const float* __restrict__ src, int srcStride,
                              int colOff,
                              __half* __restrict__ hi,
                              __half* __restrict__ lo, int n4)
{
    int idx = blockIdx.x * blockDim.x + threadIdx.x;
    if (idx >= n4) return;
    int row = idx / (KVDIM / 4);
    int c4  = idx % (KVDIM / 4);
    float4 v = *(const float4*)(src + (size_t)row * srcStride + colOff + c4 * 4);
    __half2 h01 = __floats2half2_rn(v.x, v.y);
    __half2 h23 = __floats2half2_rn(v.z, v.w);
    __half2 l01 = __floats2half2_rn(v.x - __half2float(__low2half(h01)),
                                    v.y - __half2float(__high2half(h01)));
    __half2 l23 = __floats2half2_rn(v.z - __half2float(__low2half(h23)),
                                    v.w - __half2float(__high2half(h23)));
    size_t o = (size_t)row * (KVDIM / 2) + c4 * 2;
    ((__half2*)hi)[o]     = h01;
    ((__half2*)hi)[o + 1] = h23;
    ((__half2*)lo)[o]     = l01;
    ((__half2*)lo)[o + 1] = l23;
}

// ============================================================================
// Tensor-core flash attention (causal, GQA), fp16x3-split.
// grid = (SEQ/64, NH), 128 threads; qb order reversed (longest CTAs first).
// Epilogue writes the fp16 hi/lo split of O directly (feeds the wo GEMM).
// ============================================================================
#define LDB   136
#define ATILE (64 * LDB)
#define ASMEM (6 * ATILE * 2)    // 104448 B -> 2 CTAs/SM

__global__ __launch_bounds__(128) void attn_mma(
    const __half* __restrict__ Qh, const __half* __restrict__ Ql,
    const __half* __restrict__ Kh, const __half* __restrict__ Kl,
    const __half* __restrict__ Vh, const __half* __restrict__ Vl,
    __half* __restrict__ Oh, __half* __restrict__ Ol)
{
    extern __shared__ __half sma[];
    const u32 sQh = (u32)__cvta_generic_to_shared(sma);
    const u32 sQl = sQh + ATILE * 2;
    const u32 sKh = sQl + ATILE * 2;
    const u32 sKl = sKh + ATILE * 2;
    const u32 sVh = sKl + ATILE * 2;
    const u32 sVl = sVh + ATILE * 2;

    const int tid  = threadIdx.x;
    const int lane = tid & 31;
    const int warp = tid >> 5;
    const int qb   = gridDim.x - 1 - blockIdx.x;   // longest blocks first
    const int h    = blockIdx.y;
    const int kvh  = h >> 2;
    const int g    = lane >> 2;
    const int tig  = lane & 3;

    const int lrow  = tid >> 1;
    const int lhalf = (tid & 1) * 64;
    const u32 sOff  = (u32)(lrow * LDB + lhalf) * 2;

    {
        size_t qo = ((size_t)(qb * 64 + lrow) * NH + h) * HD + lhalf;
        #pragma unroll
        for (int c = 0; c < 8; c++) {
            cp16(sQh + sOff + c * 16, Qh + qo + c * 8);
            cp16(sQl + sOff + c * 16, Ql + qo + c * 8);
        }
        asm volatile("cp.async.commit_group;\n");
    }

    const u32 aO = (u32)((warp * 16 + (lane & 15)) * LDB) * 2 + (lane >> 4) * 16;
    const u32 bO = (u32)(((lane & 7) + ((lane >> 4) & 1) * 8) * LDB) * 2
                 + ((lane >> 3) & 1) * 16;
    const u32 vO = (u32)((lane & 15) * LDB) * 2 + (lane >> 4) * 16;

    float m[2] = {-1e30f, -1e30f}, l[2] = {0.f, 0.f};
    float acc[16][4];
    #pragma unroll
    for (int nt = 0; nt < 16; nt++)
        #pragma unroll
        for (int c = 0; c < 4; c++) acc[nt][c] = 0.f;

    for (int j = 0; j <= qb; j++) {
        __syncthreads();
        {
            size_t ko = ((size_t)(j * 64 + lrow) * NKV + kvh) * HD + lhalf;
            #pragma unroll
            for (int c = 0; c < 8; c++) {
                cp16(sKh + sOff + c * 16, Kh + ko + c * 8);
                cp16(sKl + sOff + c * 16, Kl + ko + c * 8);
                cp16(sVh + sOff + c * 16, Vh + ko + c * 8);
                cp16(sVl + sOff + c * 16, Vl + ko + c * 8);
            }
            asm volatile("cp.async.commit_group;\n");
            asm volatile("cp.async.wait_group 0;\n");
        }
        __syncthreads();

        float sv[8][4];
        #pragma unroll
        for (int nt = 0; nt < 8; nt++)
            #pragma unroll
            for (int c = 0; c < 4; c++) sv[nt][c] = 0.f;

        #pragma unroll
        for (int ks = 0; ks < 8; ks++) {
            const u32 kb = ks * 32;
            u32 ah[4], al[4];
            ldsm4(ah, sQh + aO + kb);
            ldsm4(al, sQl + aO + kb);
            #pragma unroll
            for (int np = 0; np < 4; np++) {
                u32 bh[4], bl[4];
                ldsm4(bh, sKh + bO + np * (16 * LDB * 2) + kb);
                ldsm4(bl, sKl + bO + np * (16 * LDB * 2) + kb);
                mma16816(sv[2 * np],     ah, &bh[0]);
                mma16816(sv[2 * np],     al, &bh[0]);
                mma16816(sv[2 * np],     ah, &bl[0]);
                mma16816(sv[2 * np + 1], ah, &bh[2]);
                mma16816(sv[2 * np + 1], al, &bh[2]);
                mma16816(sv[2 * np + 1], ah, &bl[2]);
            }
        }

        if (j == qb) {
            #pragma unroll
            for (int nt = 0; nt < 8; nt++)
                #pragma unroll
                for (int c = 0; c < 4; c++) {
                    int col = nt * 8 + tig * 2 + (c & 1);
                    int row = warp * 16 + g + (c >> 1) * 8;
                    if (col > row) sv[nt][c] = -1e30f;
                }
        }

        #pragma unroll
        for (int half = 0; half < 2; half++) {
            float rm = -1e30f;
            #pragma unroll
            for (int nt = 0; nt < 8; nt++)
                rm = fmaxf(rm, fmaxf(sv[nt][half * 2], sv[nt][half * 2 + 1]));
            rm = fmaxf(rm, __shfl_xor_sync(0xffffffffu, rm, 1));
            rm = fmaxf(rm, __shfl_xor_sync(0xffffffffu, rm, 2));
            float mn   = fmaxf(m[half], rm);
            float corr = __expf(m[half] - mn);
            float rs = 0.f;
            #pragma unroll
            for (int nt = 0; nt < 8; nt++) {
                float p0 = __expf(sv[nt][half * 2]     - mn);
                float p1 = __expf(sv[nt][half * 2 + 1] - mn);
                sv[nt][half * 2]     = p0;
                sv[nt][half * 2 + 1] = p1;
                rs += p0 + p1;
            }
            rs += __shfl_xor_sync(0xffffffffu, rs, 1);
            rs += __shfl_xor_sync(0xffffffffu, rs, 2);
            l[half] = l[half] * corr + rs;
            m[half] = mn;
            #pragma unroll
            for (int nt = 0; nt < 16; nt++) {
                acc[nt][half * 2]     *= corr;
                acc[nt][half * 2 + 1] *= corr;
            }
        }
        __syncwarp();

        #pragma unroll
        for (int ks = 0; ks < 4; ks++) {
            u32 pa_h[4], pa_l[4];
            #pragma unroll
            for (int t = 0; t < 2; t++) {
                float p0 = sv[2 * ks + t][0], p1 = sv[2 * ks + t][1];
                float p2 = sv[2 * ks + t][2], p3 = sv[2 * ks + t][3];
                __half2 h01 = __floats2half2_rn(p0, p1);
                __half2 h23 = __floats2half2_rn(p2, p3);
                __half2 l01 = __floats2half2_rn(p0 - __half2float(__low2half(h01)),
                                                p1 - __half2float(__high2half(h01)));
                __half2 l23 = __floats2half2_rn(p2 - __half2float(__low2half(h23)),
                                                p3 - __half2float(__high2half(h23)));
                pa_h[2 * t]     = *(u32*)&h01;
                pa_h[2 * t + 1] = *(u32*)&h23;
                pa_l[2 * t]     = *(u32*)&l01;
                pa_l[2 * t + 1] = *(u32*)&l23;
            }
            const u32 kb = (u32)(ks * 16 * LDB) * 2;
            #pragma unroll
            for (int np = 0; np < 8; np++) {
                u32 vh[4], vl[4];
                ldsm4t(vh, sVh + vO + kb + np * 32);
                ldsm4t(vl, sVl + vO + kb + np * 32);
                mma16816(acc[2 * np],     pa_h, &vh[0]);
                mma16816(acc[2 * np],     pa_l, &vh[0]);
                mma16816(acc[2 * np],     pa_h, &vl[0]);
                mma16816(acc[2 * np + 1], pa_h, &vh[2]);
                mma16816(acc[2 * np + 1], pa_l, &vh[2]);
                mma16816(acc[2 * np + 1], pa_h, &vl[2]);
            }
        }
    }

    // ---- epilogue: normalize + fp16 hi/lo split, write directly ----
    #pragma unroll
    for (int half = 0; half < 2; half++) {
        float inv = 1.0f / l[half];
        int row = qb * 64 + warp * 16 + g + half * 8;
        size_t base = (size_t)row * DIM + h * HD;
        #pragma unroll
        for (int nt = 0; nt < 16; nt++) {
            int col = nt * 8 + tig * 2;
            float v0 = acc[nt][half * 2] * inv;
            float v1 = acc[nt][half * 2 + 1] * inv;
            __half2 hh = __floats2half2_rn(v0, v1);
            __half2 ll = __floats2half2_rn(v0 - __half2float(__low2half(hh)),
                                           v1 - __half2float(__high2half(hh)));
            *(__half2*)(Oh + base + col) = hh;
            *(__half2*)(Ol + base + col) = ll;
        }
    }
}

// ============================================================================
// kernel_launch
// ============================================================================
extern "C" void kernel_launch(void* const* d_in, const int* in_sizes, int n_in,
                              void* d_out, int out_size)
{
    const float* x  = (const float*)d_in[0];
    const float* wq = (const float*)d_in[1];
    const float* wk = (const float*)d_in[2];
    const float* wv = (const float*)d_in[3];
    const float* wo = (const float*)d_in[4];
    float* out = (float*)d_out;

    float* QKV;
    cudaGetSymbolAddress((void**)&QKV, g_QKV);
    __half *xh, *xl, *wh, *wl, *woh, *wol, *ah, *al;
    __half *qbh, *qbl, *kbh, *kbl, *vbh, *vbl;
    cudaGetSymbolAddress((void**)&xh,  g_xh);  cudaGetSymbolAddress((void**)&xl,  g_xl);
    cudaGetSymbolAddress((void**)&wh,  g_wh);  cudaGetSymbolAddress((void**)&wl,  g_wl);
    cudaGetSymbolAddress((void**)&woh, g_woh); cudaGetSymbolAddress((void**)&wol, g_wol);
    cudaGetSymbolAddress((void**)&ah,  g_ah);  cudaGetSymbolAddress((void**)&al,  g_al);
    cudaGetSymbolAddress((void**)&qbh, g_qbh); cudaGetSymbolAddress((void**)&qbl, g_qbl);
    cudaGetSymbolAddress((void**)&kbh, g_kbh); cudaGetSymbolAddress((void**)&kbl, g_kbl);
    cudaGetSymbolAddress((void**)&vbh, g_vbh); cudaGetSymbolAddress((void**)&vbl, g_vbl);

    cudaFuncSetAttribute(gemm_fp16x3,
                         cudaFuncAttributeMaxDynamicSharedMemorySize, GSMEM);
    cudaFuncSetAttribute(attn_mma,
                         cudaFuncAttributeMaxDynamicSharedMemorySize, ASMEM);

    // 1) split x; transpose+split weights into the fused [6144][4096] buffer
    split_kernel<<<(SEQ * DIM / 4 + 255) / 256, 256>>>(x, xh, xl, SEQ * DIM / 4);
    transpose_split_kernel<<<dim3(DIM   / 32, DIM / 32), dim3(32, 8)>>>(
        wq, wh, wl, DIM, DIM);
    transpose_split_kernel<<<dim3(KVDIM / 32, DIM / 32), dim3(32, 8)>>>(
        wk, wh + (size_t)DIM * DIM, wl + (size_t)DIM * DIM, DIM, KVDIM);
    transpose_split_kernel<<<dim3(KVDIM / 32, DIM / 32), dim3(32, 8)>>>(
        wv, wh + (size_t)(DIM + KVDIM) * DIM, wl + (size_t)(DIM + KVDIM) * DIM, DIM, KVDIM);
    transpose_split_kernel<<<dim3(DIM   / 32, DIM / 32), dim3(32, 8)>>>(
        wo, woh, wol, DIM, DIM);

    // 2) fused QKV projection (one GEMM: N = 6144)
    gemm_fp16x3<<<dim3(QKVN / 128, SEQ / 128), 256, GSMEM>>>(
        xh, xl, wh, wl, QKV, SEQ, QKVN, DIM);

    // 3) RoPE + fp16 split (fold 1/sqrt(HD) into Q); strided split for V
    const float scale = 0.08838834764831845f;
    int nq = SEQ * NH  * (HD / 2);
    int nk = SEQ * NKV * (HD / 2);
    rope_split_kernel<<<(nq + 255) / 256, 256>>>(QKV, QKVN, 0,    qbh, qbl, NH,  scale);
    rope_split_kernel<<<(nk + 255) / 256, 256>>>(QKV, QKVN, DIM,  kbh, kbl, NKV, 1.0f);
    vsplit_kernel<<<(SEQ * KVDIM / 4 + 255) / 256, 256>>>(
        QKV, QKVN, DIM + KVDIM, vbh, vbl, SEQ * KVDIM / 4);

    // 4) tensor-core attention (epilogue writes split O directly)
    attn_mma<<<dim3(SEQ / 64, NH), 128, ASMEM>>>(qbh, qbl, kbh, kbl, vbh, vbl, ah, al);

    // 5) output projection
    gemm_fp16x3<<<dim3(DIM / 128, SEQ / 128), 256, GSMEM>>>(
        ah, al, woh, wol, out, SEQ, DIM, DIM);
}

// round 15
// speedup vs baseline: 1.3534x; 1.0689x over previous
#include <cuda_runtime.h>
#include <cuda_fp16.h>
#include <math.h>

// Problem constants
#define SEQ   2048
#define DIM   4096
#define NH    32
#define NKV   8
#define HD    128
#define KVDIM (NKV * HD)     // 1024
#define QKVN  (DIM + 2 * KVDIM)  // 6144

typedef unsigned int u32;

// -------- scratch (device globals; no runtime allocation allowed) --------
__device__ __half g_xh[SEQ * DIM],   g_xl[SEQ * DIM];  // split x
__device__ __half g_wh[QKVN * DIM],  g_wl[QKVN * DIM]; // wq|wk|wv transposed [N][K]
__device__ __half g_woh[DIM * DIM],  g_wol[DIM * DIM]; // wol written, unused (2-term wo)
__device__ __half g_ah[SEQ * DIM],   g_al[SEQ * DIM];  // attention out (split)
__device__ __half g_qbh[SEQ * DIM],   g_qbl[SEQ * DIM];
__device__ __half g_kbh[SEQ * KVDIM], g_kbl[SEQ * KVDIM];
__device__ __half g_vbh[SEQ * KVDIM];                  // V hi only (2-term PV)

// ============================================================================
// PTX primitives (legacy tensor path — tcgen05 not supported by this build)
// ============================================================================
__device__ __forceinline__ void ldsm4(u32* r, u32 addr) {
    asm volatile("ldmatrix.sync.aligned.m8n8.x4.shared.b16 {%0,%1,%2,%3}, [%4];\n"
        : "=r"(r[0]), "=r"(r[1]), "=r"(r[2]), "=r"(r[3]) : "r"(addr));
}
__device__ __forceinline__ void ldsm4t(u32* r, u32 addr) {
    asm volatile("ldmatrix.sync.aligned.m8n8.x4.trans.shared.b16 {%0,%1,%2,%3}, [%4];\n"
        : "=r"(r[0]), "=r"(r[1]), "=r"(r[2]), "=r"(r[3]) : "r"(addr));
}
__device__ __forceinline__ void mma16816(float* c, const u32* a, const u32* b) {
    asm volatile("mma.sync.aligned.m16n8k16.row.col.f32.f16.f16.f32 "
        "{%0,%1,%2,%3}, {%4,%5,%6,%7}, {%8,%9}, {%0,%1,%2,%3};\n"
        : "+f"(c[0]), "+f"(c[1]), "+f"(c[2]), "+f"(c[3])
        : "r"(a[0]), "r"(a[1]), "r"(a[2]), "r"(a[3]), "r"(b[0]), "r"(b[1]));
}
__device__ __forceinline__ void cp16(u32 dst, const void* src) {
    asm volatile("cp.async.cg.shared.global [%0], [%1], 16;\n" :: "r"(dst), "l"(src));
}
__device__ __forceinline__ __half2 split_pair(float v0, float v1, __half2* lo) {
    __half2 hh = __floats2half2_rn(v0, v1);
    *lo = __floats2half2_rn(v0 - __half2float(__low2half(hh)),
                            v1 - __half2float(__high2half(hh)));
    return hh;
}

// ============================================================================
// Split fp32 -> fp16 hi + fp16 lo(residual). Vectorized x4.
// ============================================================================
__global__ void split_kernel(const float* __restrict__ in,
                             __half* __restrict__ hi,
                             __half* __restrict__ lo, int n4)
{
    int i = blockIdx.x * blockDim.x + threadIdx.x;
    if (i >= n4) return;
    float4 v = ((const float4*)in)[i];
    __half2 l01, l23;
    __half2 h01 = split_pair(v.x, v.y, &l01);
    __half2 h23 = split_pair(v.z, v.w, &l23);
    ((__half2*)hi)[2 * i]     = h01;
    ((__half2*)hi)[2 * i + 1] = h23;
    ((__half2*)lo)[2 * i]     = l01;
    ((__half2*)lo)[2 * i + 1] = l23;
}

// ============================================================================
// Transpose + split: in fp32 [K][N] -> hi/lo fp16 [N][K].
// ============================================================================
__global__ void transpose_split_kernel(const float* __restrict__ in,
                                       __half* __restrict__ hi,
                                       __half* __restrict__ lo,
                                       int K, int N)
{
    __shared__ float t[32][33];
    int n0 = blockIdx.x * 32, k0 = blockIdx.y * 32;
    int tx = threadIdx.x, ty = threadIdx.y;   // (32, 8)
    #pragma unroll
    for (int i = 0; i < 4; i++)
        t[ty + i * 8][tx] = in[(size_t)(k0 + ty + i * 8) * N + n0 + tx];
    __syncthreads();
    #pragma unroll
    for (int i = 0; i < 4; i++) {
        float v = t[tx][ty + i * 8];
        __half h = __float2half_rn(v);
        size_t o = (size_t)(n0 + ty + i * 8) * K + k0 + tx;
        hi[o] = h;
        lo[o] = __float2half_rn(v - __half2float(h));
    }
}

// ============================================================================
// fp16-split tensor-core GEMM: C[M,N] fp32 = A @ B^T
//   A: hi/lo fp16 [M][K];  B: hi/lo fp16 [N][K] (K-major)
// TERMS=3: AhBh + AlBh + AhBl.  TERMS=2: AhBh + AlBh (B fp16-quantized).
// EPI=0: fp32 C.  EPI=1: fused RoPE + fp16 hi/lo split straight into the
//        Q/K/V attention operand buffers (no fp32 intermediate).
// 128x128x32 tiles, 256 threads, cp.async double-buffered (2 CTAs/SM).
// ============================================================================
#define GBK   32
#define GLD   40                 // padded row stride in halfs
#define GTILE (128 * GLD)        // halfs per tile buffer
#define GTILEB (GTILE * 2)       // 10240 bytes
#define GSMEM (8 * GTILEB)       // 81920 B

template<int TERMS, int EPI>
__global__ __launch_bounds__(256) void gemm_fp16x3(
    const __half* __restrict__ Ah, const __half* __restrict__ Al,
    const __half* __restrict__ Bh, const __half* __restrict__ Bl,
    float* __restrict__ C, int M, int N, int K,
    __half* __restrict__ qh, __half* __restrict__ ql,
    __half* __restrict__ kh, __half* __restrict__ kl,
    __half* __restrict__ vh)
{
    extern __shared__ __half smg[];
    __half* sAh = smg;
    __half* sAl = sAh + 2 * GTILE;
    __half* sBh = sAl + 2 * GTILE;
    __half* sBl = sBh + 2 * GTILE;

    const int tid  = threadIdx.x;
    const int lane = tid & 31;
    const int warp = tid >> 5;
    const int wm   = warp & 3;    // 0..3 -> 32-row slab
    const int wn   = warp >> 2;   // 0..1 -> 64-col slab
    const int m0   = blockIdx.y * 128;
    const int n0   = blockIdx.x * 128;

    const u32 sAh0 = (u32)__cvta_generic_to_shared(sAh);
    const u32 sAl0 = (u32)__cvta_generic_to_shared(sAl);
    const u32 sBh0 = (u32)__cvta_generic_to_shared(sBh);
    const u32 sBl0 = (u32)__cvta_generic_to_shared(sBl);

    // loader: 2 x 16B per tile per thread (rows r, r+64)
    const int lrow = tid >> 2;            // 0..63
    const int lkc  = (tid & 3) * 8;       // half col 0,8,16,24
    const size_t gA = (size_t)(m0 + lrow) * K + lkc;
    const size_t gB = (size_t)(n0 + lrow) * K + lkc;
    const u32 sOff  = (u32)(lrow * GLD + lkc) * 2;
    const u32 sOff2 = sOff + 64 * GLD * 2;

    float acc[2][8][4];
    #pragma unroll
    for (int a = 0; a < 2; a++)
        #pragma unroll
        for (int b = 0; b < 8; b++)
            #pragma unroll
            for (int c = 0; c < 4; c++) acc[a][b][c] = 0.f;

    const u32 aOff = (u32)((wm * 32 + (lane & 15)) * GLD + (lane >> 4) * 8) * 2;
    const u32 bOff = (u32)((wn * 64 + (lane & 7) + ((lane >> 4) & 1) * 8) * GLD
                           + ((lane >> 3) & 1) * 8) * 2;

    const int nk = K / GBK;

    // prologue: stage 0
    {
        cp16(sAh0 + sOff,  Ah + gA);  cp16(sAh0 + sOff2, Ah + gA + (size_t)64 * K);
        cp16(sAl0 + sOff,  Al + gA);  cp16(sAl0 + sOff2, Al + gA + (size_t)64 * K);
        cp16(sBh0 + sOff,  Bh + gB);  cp16(sBh0 + sOff2, Bh + gB + (size_t)64 * K);
        if (TERMS == 3) {
            cp16(sBl0 + sOff,  Bl + gB);
            cp16(sBl0 + sOff2, Bl + gB + (size_t)64 * K);
        }
        asm volatile("cp.async.commit_group;\n");
    }

    for (int it = 0; it < nk; it++) {
        if (it + 1 < nk) {
            const int kk = (it + 1) * GBK;
            const u32 sb = (u32)(((it + 1) & 1) * GTILEB);
            cp16(sAh0 + sb + sOff,  Ah + gA + kk);
            cp16(sAh0 + sb + sOff2, Ah + gA + kk + (size_t)64 * K);
            cp16(sAl0 + sb + sOff,  Al + gA + kk);
            cp16(sAl0 + sb + sOff2, Al + gA + kk + (size_t)64 * K);
            cp16(sBh0 + sb + sOff,  Bh + gB + kk);
            cp16(sBh0 + sb + sOff2, Bh + gB + kk + (size_t)64 * K);
            if (TERMS == 3) {
                cp16(sBl0 + sb + sOff,  Bl + gB + kk);
                cp16(sBl0 + sb + sOff2, Bl + gB + kk + (size_t)64 * K);
            }
            asm volatile("cp.async.commit_group;\n");
            asm volatile("cp.async.wait_group 1;\n");
        } else {
            asm volatile("cp.async.wait_group 0;\n");
        }
        __syncthreads();

        const u32 sb = (u32)((it & 1) * GTILEB);
        #pragma unroll
        for (int ks = 0; ks < 2; ks++) {
            const u32 kb = sb + ks * 32;    // k16 step = 32 bytes
            u32 a_hi[2][4], a_lo[2][4], b_hi[4][4], b_lo[4][4];
            #pragma unroll
            for (int mt = 0; mt < 2; mt++) {
                ldsm4(a_hi[mt], sAh0 + kb + aOff + mt * (16 * GLD * 2));
                ldsm4(a_lo[mt], sAl0 + kb + aOff + mt * (16 * GLD * 2));
            }
            #pragma unroll
            for (int np = 0; np < 4; np++) {
                ldsm4(b_hi[np], sBh0 + kb + bOff + np * (16 * GLD * 2));
                if (TERMS == 3)
                    ldsm4(b_lo[np], sBl0 + kb + bOff + np * (16 * GLD * 2));
            }
            #pragma unroll
            for (int mt = 0; mt < 2; mt++)
                #pragma unroll
                for (int nt = 0; nt < 8; nt++) {
                    const u32* bh = &b_hi[nt >> 1][(nt & 1) * 2];
                    mma16816(acc[mt][nt], a_hi[mt], bh);
                    mma16816(acc[mt][nt], a_lo[mt], bh);
                    if (TERMS == 3) {
                        const u32* bl = &b_lo[nt >> 1][(nt & 1) * 2];
                        mma16816(acc[mt][nt], a_hi[mt], bl);
                    }
                }
        }
        __syncthreads();
    }

    const int erow = m0 + wm * 32 + (lane >> 2);
    const int ecol = n0 + wn * 64 + (lane & 3) * 2;

    if (EPI == 0) {
        // plain fp32 output
        #pragma unroll
        for (int mt = 0; mt < 2; mt++)
            #pragma unroll
            for (int nt = 0; nt < 8; nt++) {
                int r = erow + mt * 16;
                int c = ecol + nt * 8;
                *(float2*)&C[(size_t)r * N + c] =
                    make_float2(acc[mt][nt][0], acc[mt][nt][1]);
                *(float2*)&C[(size_t)(r + 8) * N + c] =
                    make_float2(acc[mt][nt][2], acc[mt][nt][3]);
            }
    } else {
        // fused RoPE + fp16 hi/lo split into attention operand buffers.
        // Region uniform per CTA (boundaries 4096/5120 are 128-multiples).
        const int region = (n0 < DIM) ? 0 : ((n0 < DIM + KVDIM) ? 1 : 2);
        const float qscale = 0.08838834764831845f;   // 1/sqrt(128)
        float invf[8];
        #pragma unroll
        for (int nt = 0; nt < 8; nt++) {
            int c = ecol + nt * 8;
            invf[nt] = powf(10000.0f, -(float)(c & 127) / 128.0f);
        }
        #pragma unroll
        for (int mt = 0; mt < 2; mt++)
            #pragma unroll
            for (int nt = 0; nt < 8; nt++) {
                int c = ecol + nt * 8;
                #pragma unroll
                for (int hrow = 0; hrow < 2; hrow++) {
                    int r = erow + mt * 16 + hrow * 8;
                    float v0 = acc[mt][nt][hrow * 2];
                    float v1 = acc[mt][nt][hrow * 2 + 1];
                    if (region == 2) {
                        // V: plain fp16 convert (hi only; PV is 2-term)
                        size_t o = (size_t)r * KVDIM + (c - DIM - KVDIM);
                        *(__half2*)(vh + o) = __floats2half2_rn(v0, v1);
                    } else {
                        float sn, cs;
                        sincosf((float)r * invf[nt], &sn, &cs);
                        float o0 = v0 * cs - v1 * sn;
                        float o1 = v0 * sn + v1 * cs;
                        if (region == 0) { o0 *= qscale; o1 *= qscale; }
                        __half2 ll;
                        __half2 hh = split_pair(o0, o1, &ll);
                        if (region == 0) {
                            size_t o = (size_t)r * DIM + c;
                            *(__half2*)(qh + o) = hh;
                            *(__half2*)(ql + o) = ll;
                        } else {
                            size_t o = (size_t)r * KVDIM + (c - DIM);
                            *(__half2*)(kh + o) = hh;
                            *(__half2*)(kl + o) = ll;
                        }
                    }
                }
            }
    }
}

// ============================================================================
// Tensor-core flash attention (causal, GQA), fp16-split.
// S = QhKh + QlKh + QhKl (3-term);  O += PhVh + PlVh (2-term, V fp16).
// grid = (SEQ/64, NH), 128 threads; longest CTAs scheduled first.
// Epilogue writes the fp16 hi/lo split of O directly (feeds the wo GEMM).
// ============================================================================
#define LDB   136
#define ATILE (64 * LDB)
#define ASMEM (5 * ATILE * 2)    // Qh,Ql,Kh,Kl,Vh = 87040 B -> 2 CTAs/SM

__global__ __launch_bounds__(128) void attn_mma(
    const __half* __restrict__ Qh, const __half* __restrict__ Ql,
    const __half* __restrict__ Kh, const __half* __restrict__ Kl,
    const __half* __restrict__ Vh,
    __half* __restrict__ Oh, __half* __restrict__ Ol)
{
    extern __shared__ __half sma[];
    const u32 sQh = (u32)__cvta_generic_to_shared(sma);
    const u32 sQl = sQh + ATILE * 2;
    const u32 sKh = sQl + ATILE * 2;
    const u32 sKl = sKh + ATILE * 2;
    const u32 sVh = sKl + ATILE * 2;

    const int tid  = threadIdx.x;
    const int lane = tid & 31;
    const int warp = tid >> 5;
    const int qb   = gridDim.x - 1 - blockIdx.x;   // longest blocks first
    const int h    = blockIdx.y;
    const int kvh  = h >> 2;
    const int g    = lane >> 2;
    const int tig  = lane & 3;

    const int lrow  = tid >> 1;
    const int lhalf = (tid & 1) * 64;
    const u32 sOff  = (u32)(lrow * LDB + lhalf) * 2;

    {
        size_t qo = ((size_t)(qb * 64 + lrow) * NH + h) * HD + lhalf;
        #pragma unroll
        for (int c = 0; c < 8; c++) {
            cp16(sQh + sOff + c * 16, Qh + qo + c * 8);
            cp16(sQl + sOff + c * 16, Ql + qo + c * 8);
        }
        asm volatile("cp.async.commit_group;\n");
    }

    const u32 aO = (u32)((warp * 16 + (lane & 15)) * LDB) * 2 + (lane >> 4) * 16;
    const u32 bO = (u32)(((lane & 7) + ((lane >> 4) & 1) * 8) * LDB) * 2
                 + ((lane >> 3) & 1) * 16;
    const u32 vO = (u32)((lane & 15) * LDB) * 2 + (lane >> 4) * 16;

    float m[2] = {-1e30f, -1e30f}, l[2] = {0.f, 0.f};
    float acc[16][4];
    #pragma unroll
    for (int nt = 0; nt < 16; nt++)
        #pragma unroll
        for (int c = 0; c < 4; c++) acc[nt][c] = 0.f;

    for (int j = 0; j <= qb; j++) {
        __syncthreads();
        {
            size_t ko = ((size_t)(j * 64 + lrow) * NKV + kvh) * HD + lhalf;
            #pragma unroll
            for (int c = 0; c < 8; c++) {
                cp16(sKh + sOff + c * 16, Kh + ko + c * 8);
                cp16(sKl + sOff + c * 16, Kl + ko + c * 8);
                cp16(sVh + sOff + c * 16, Vh + ko + c * 8);
            }
            asm volatile("cp.async.commit_group;\n");
            asm volatile("cp.async.wait_group 0;\n");
        }
        __syncthreads();

        float sv[8][4];
        #pragma unroll
        for (int nt = 0; nt < 8; nt++)
            #pragma unroll
            for (int c = 0; c < 4; c++) sv[nt][c] = 0.f;

        #pragma unroll
        for (int ks = 0; ks < 8; ks++) {
            const u32 kb = ks * 32;
            u32 ah[4], al[4];
            ldsm4(ah, sQh + aO + kb);
            ldsm4(al, sQl + aO + kb);
            #pragma unroll
            for (int np = 0; np < 4; np++) {
                u32 bh[4], bl[4];
                ldsm4(bh, sKh + bO + np * (16 * LDB * 2) + kb);
                ldsm4(bl, sKl + bO + np * (16 * LDB * 2) + kb);
                mma16816(sv[2 * np],     ah, &bh[0]);
                mma16816(sv[2 * np],     al, &bh[0]);
                mma16816(sv[2 * np],     ah, &bl[0]);
                mma16816(sv[2 * np + 1], ah, &bh[2]);
                mma16816(sv[2 * np + 1], al, &bh[2]);
                mma16816(sv[2 * np + 1], ah, &bl[2]);
            }
        }

        if (j == qb) {
            #pragma unroll
            for (int nt = 0; nt < 8; nt++)
                #pragma unroll
                for (int c = 0; c < 4; c++) {
                    int col = nt * 8 + tig * 2 + (c & 1);
                    int row = warp * 16 + g + (c >> 1) * 8;
                    if (col > row) sv[nt][c] = -1e30f;
                }
        }

        #pragma unroll
        for (int half = 0; half < 2; half++) {
            float rm = -1e30f;
            #pragma unroll
            for (int nt = 0; nt < 8; nt++)
                rm = fmaxf(rm, fmaxf(sv[nt][half * 2], sv[nt][half * 2 + 1]));
            rm = fmaxf(rm, __shfl_xor_sync(0xffffffffu, rm, 1));
            rm = fmaxf(rm, __shfl_xor_sync(0xffffffffu, rm, 2));
            float mn   = fmaxf(m[half], rm);
            float corr = __expf(m[half] - mn);
            float rs = 0.f;
            #pragma unroll
            for (int nt = 0; nt < 8; nt++) {
                float p0 = __expf(sv[nt][half * 2]     - mn);
                float p1 = __expf(sv[nt][half * 2 + 1] - mn);
                sv[nt][half * 2]     = p0;
                sv[nt][half * 2 + 1] = p1;
                rs += p0 + p1;
            }
            rs += __shfl_xor_sync(0xffffffffu, rs, 1);
            rs += __shfl_xor_sync(0xffffffffu, rs, 2);
            l[half] = l[half] * corr + rs;
            m[half] = mn;
            #pragma unroll
            for (int nt = 0; nt < 16; nt++) {
                acc[nt][half * 2]     *= corr;
                acc[nt][half * 2 + 1] *= corr;
            }
        }
        __syncwarp();

        #pragma unroll
        for (int ks = 0; ks < 4; ks++) {
            u32 pa_h[4], pa_l[4];
            #pragma unroll
            for (int t = 0; t < 2; t++) {
                __half2 l01, l23;
                __half2 h01 = split_pair(sv[2 * ks + t][0], sv[2 * ks + t][1], &l01);
                __half2 h23 = split_pair(sv[2 * ks + t][2], sv[2 * ks + t][3], &l23);
                pa_h[2 * t]     = *(u32*)&h01;
                pa_h[2 * t + 1] = *(u32*)&h23;
                pa_l[2 * t]     = *(u32*)&l01;
                pa_l[2 * t + 1] = *(u32*)&l23;
            }
            const u32 kb = (u32)(ks * 16 * LDB) * 2;
            #pragma unroll
            for (int np = 0; np < 8; np++) {
                u32 vh[4];
                ldsm4t(vh, sVh + vO + kb + np * 32);
                mma16816(acc[2 * np],     pa_h, &vh[0]);
                mma16816(acc[2 * np],     pa_l, &vh[0]);
                mma16816(acc[2 * np + 1], pa_h, &vh[2]);
                mma16816(acc[2 * np + 1], pa_l, &vh[2]);
            }
        }
    }

    // ---- epilogue: normalize + fp16 hi/lo split, write directly ----
    #pragma unroll
    for (int half = 0; half < 2; half++) {
        float inv = 1.0f / l[half];
        int row = qb * 64 + warp * 16 + g + half * 8;
        size_t base = (size_t)row * DIM + h * HD;
        #pragma unroll
        for (int nt = 0; nt < 16; nt++) {
            int col = nt * 8 + tig * 2;
            __half2 ll;
            __half2 hh = split_pair(acc[nt][half * 2] * inv,
                                    acc[nt][half * 2 + 1] * inv, &ll);
            *(__half2*)(Oh + base + col) = hh;
            *(__half2*)(Ol + base + col) = ll;
        }
    }
}

// ============================================================================
// kernel_launch
// ============================================================================
extern "C" void kernel_launch(void* const* d_in, const int* in_sizes, int n_in,
                              void* d_out, int out_size)
{
    const float* x  = (const float*)d_in[0];
    const float* wq = (const float*)d_in[1];
    const float* wk = (const float*)d_in[2];
    const float* wv = (const float*)d_in[3];
    const float* wo = (const float*)d_in[4];
    float* out = (float*)d_out;

    __half *xh, *xl, *wh, *wl, *woh, *wol, *ah, *al;
    __half *qbh, *qbl, *kbh, *kbl, *vbh;
    cudaGetSymbolAddress((void**)&xh,  g_xh);  cudaGetSymbolAddress((void**)&xl,  g_xl);
    cudaGetSymbolAddress((void**)&wh,  g_wh);  cudaGetSymbolAddress((void**)&wl,  g_wl);
    cudaGetSymbolAddress((void**)&woh, g_woh); cudaGetSymbolAddress((void**)&wol, g_wol);
    cudaGetSymbolAddress((void**)&ah,  g_ah);  cudaGetSymbolAddress((void**)&al,  g_al);
    cudaGetSymbolAddress((void**)&qbh, g_qbh); cudaGetSymbolAddress((void**)&qbl, g_qbl);
    cudaGetSymbolAddress((void**)&kbh, g_kbh); cudaGetSymbolAddress((void**)&kbl, g_kbl);
    cudaGetSymbolAddress((void**)&vbh, g_vbh);

    cudaFuncSetAttribute(gemm_fp16x3<3, 1>,
                         cudaFuncAttributeMaxDynamicSharedMemorySize, GSMEM);
    cudaFuncSetAttribute(gemm_fp16x3<2, 0>,
                         cudaFuncAttributeMaxDynamicSharedMemorySize, GSMEM);
    cudaFuncSetAttribute(attn_mma,
                         cudaFuncAttributeMaxDynamicSharedMemorySize, ASMEM);

    // 1) split x; transpose+split weights into the fused [6144][4096] buffer
    split_kernel<<<(SEQ * DIM / 4 + 255) / 256, 256>>>(x, xh, xl, SEQ * DIM / 4);
    transpose_split_kernel<<<dim3(DIM   / 32, DIM / 32), dim3(32, 8)>>>(
        wq, wh, wl, DIM, DIM);
    transpose_split_kernel<<<dim3(KVDIM / 32, DIM / 32), dim3(32, 8)>>>(
        wk, wh + (size_t)DIM * DIM, wl + (size_t)DIM * DIM, DIM, KVDIM);
    transpose_split_kernel<<<dim3(KVDIM / 32, DIM / 32), dim3(32, 8)>>>(
        wv, wh + (size_t)(DIM + KVDIM) * DIM, wl + (size_t)(DIM + KVDIM) * DIM, DIM, KVDIM);
    transpose_split_kernel<<<dim3(DIM   / 32, DIM / 32), dim3(32, 8)>>>(
        wo, woh, wol, DIM, DIM);

    // 2) fused QKV projection; epilogue applies RoPE + split in-place
    gemm_fp16x3<3, 1><<<dim3(QKVN / 128, SEQ / 128), 256, GSMEM>>>(
        xh, xl, wh, wl, nullptr, SEQ, QKVN, DIM,
        qbh, qbl, kbh, kbl, vbh);

    // 3) tensor-core attention (epilogue writes split O directly)
    attn_mma<<<dim3(SEQ / 64, NH), 128, ASMEM>>>(
        qbh, qbl, kbh, kbl, vbh, ah, al);

    // 4) output projection (2-term: wo fp16-quantized)
    gemm_fp16x3<2, 0><<<dim3(DIM / 128, SEQ / 128), 256, GSMEM>>>(
        ah, al, woh, wol, out, SEQ, DIM, DIM,
        nullptr, nullptr, nullptr, nullptr, nullptr);
}

// round 16
// speedup vs baseline: 1.7631x; 1.3027x over previous
#include <cuda_runtime.h>
#include <cuda_fp16.h>
#include <math.h>

// Problem constants
#define SEQ   2048
#define DIM   4096
#define NH    32
#define NKV   8
#define HD    128
#define KVDIM (NKV * HD)     // 1024
#define QKVN  (DIM + 2 * KVDIM)  // 6144

typedef unsigned int u32;

// -------- scratch (device globals; no runtime allocation allowed) --------
__device__ __half g_xh[SEQ * DIM],   g_xl[SEQ * DIM];  // split x
__device__ __half g_wh[QKVN * DIM];                    // wq|wk|wv fp16 [N][K]
__device__ __half g_woh[DIM * DIM];                    // wo fp16 [N][K]
__device__ __half g_ah[SEQ * DIM],   g_al[SEQ * DIM];  // attention out (split)
__device__ __half g_qbh[SEQ * DIM],   g_qbl[SEQ * DIM];
__device__ __half g_kbh[SEQ * KVDIM], g_kbl[SEQ * KVDIM];
__device__ __half g_vbh[SEQ * KVDIM];                  // V hi only (2-term PV)

// ============================================================================
// PTX primitives (legacy tensor path — tcgen05 not supported by this build)
// ============================================================================
__device__ __forceinline__ void ldsm4(u32* r, u32 addr) {
    asm volatile("ldmatrix.sync.aligned.m8n8.x4.shared.b16 {%0,%1,%2,%3}, [%4];\n"
        : "=r"(r[0]), "=r"(r[1]), "=r"(r[2]), "=r"(r[3]) : "r"(addr));
}
__device__ __forceinline__ void ldsm4t(u32* r, u32 addr) {
    asm volatile("ldmatrix.sync.aligned.m8n8.x4.trans.shared.b16 {%0,%1,%2,%3}, [%4];\n"
        : "=r"(r[0]), "=r"(r[1]), "=r"(r[2]), "=r"(r[3]) : "r"(addr));
}
__device__ __forceinline__ void mma16816(float* c, const u32* a, const u32* b) {
    asm volatile("mma.sync.aligned.m16n8k16.row.col.f32.f16.f16.f32 "
        "{%0,%1,%2,%3}, {%4,%5,%6,%7}, {%8,%9}, {%0,%1,%2,%3};\n"
        : "+f"(c[0]), "+f"(c[1]), "+f"(c[2]), "+f"(c[3])
        : "r"(a[0]), "r"(a[1]), "r"(a[2]), "r"(a[3]), "r"(b[0]), "r"(b[1]));
}
__device__ __forceinline__ void cp16(u32 dst, const void* src) {
    asm volatile("cp.async.cg.shared.global [%0], [%1], 16;\n" :: "r"(dst), "l"(src));
}
__device__ __forceinline__ __half2 split_pair(float v0, float v1, __half2* lo) {
    __half2 hh = __floats2half2_rn(v0, v1);
    *lo = __floats2half2_rn(v0 - __half2float(__low2half(hh)),
                            v1 - __half2float(__high2half(hh)));
    return hh;
}

// ============================================================================
// Split fp32 -> fp16 hi + fp16 lo(residual). Vectorized x4.
// ============================================================================
__global__ void split_kernel(const float* __restrict__ in,
                             __half* __restrict__ hi,
                             __half* __restrict__ lo, int n4)
{
    int i = blockIdx.x * blockDim.x + threadIdx.x;
    if (i >= n4) return;
    float4 v = ((const float4*)in)[i];
    __half2 l01, l23;
    __half2 h01 = split_pair(v.x, v.y, &l01);
    __half2 h23 = split_pair(v.z, v.w, &l23);
    ((__half2*)hi)[2 * i]     = h01;
    ((__half2*)hi)[2 * i + 1] = h23;
    ((__half2*)lo)[2 * i]     = l01;
    ((__half2*)lo)[2 * i + 1] = l23;
}

// ============================================================================
// Transpose (fp32 [K][N] -> fp16 [N][K], hi only — weights are fp16-quantized).
// ============================================================================
__global__ void transpose_half_kernel(const float* __restrict__ in,
                                      __half* __restrict__ hi,
                                      int K, int N)
{
    __shared__ float t[32][33];
    int n0 = blockIdx.x * 32, k0 = blockIdx.y * 32;
    int tx = threadIdx.x, ty = threadIdx.y;   // (32, 8)
    #pragma unroll
    for (int i = 0; i < 4; i++)
        t[ty + i * 8][tx] = in[(size_t)(k0 + ty + i * 8) * N + n0 + tx];
    __syncthreads();
    #pragma unroll
    for (int i = 0; i < 4; i++) {
        float v = t[tx][ty + i * 8];
        hi[(size_t)(n0 + ty + i * 8) * K + k0 + tx] = __float2half_rn(v);
    }
}

// ============================================================================
// fp16-split tensor-core GEMM: C[M,N] fp32 = A @ B^T  (2-term: AhBh + AlBh;
// B is fp16-quantized).  A: hi/lo fp16 [M][K];  B: fp16 [N][K] (K-major).
// EPI=0: fp32 C.  EPI=1: fused RoPE + fp16 hi/lo split straight into the
//        Q/K/V attention operand buffers (no fp32 intermediate).
// 128x128x32 tiles, 256 threads, cp.async double-buffered.
// ============================================================================
#define GBK   32
#define GLD   40                 // padded row stride in halfs
#define GTILE (128 * GLD)        // halfs per tile buffer
#define GTILEB (GTILE * 2)       // 10240 bytes
#define GSMEM (6 * GTILEB)       // Ah,Al,Bh x 2 stages = 61440 B

template<int EPI>
__global__ __launch_bounds__(256) void gemm_fp16x2(
    const __half* __restrict__ Ah, const __half* __restrict__ Al,
    const __half* __restrict__ Bh,
    float* __restrict__ C, int M, int N, int K,
    __half* __restrict__ qh, __half* __restrict__ ql,
    __half* __restrict__ kh, __half* __restrict__ kl,
    __half* __restrict__ vh)
{
    extern __shared__ __half smg[];
    __half* sAh = smg;
    __half* sAl = sAh + 2 * GTILE;
    __half* sBh = sAl + 2 * GTILE;

    const int tid  = threadIdx.x;
    const int lane = tid & 31;
    const int warp = tid >> 5;
    const int wm   = warp & 3;    // 0..3 -> 32-row slab
    const int wn   = warp >> 2;   // 0..1 -> 64-col slab
    const int m0   = blockIdx.y * 128;
    const int n0   = blockIdx.x * 128;

    const u32 sAh0 = (u32)__cvta_generic_to_shared(sAh);
    const u32 sAl0 = (u32)__cvta_generic_to_shared(sAl);
    const u32 sBh0 = (u32)__cvta_generic_to_shared(sBh);

    // loader: 2 x 16B per tile per thread (rows r, r+64)
    const int lrow = tid >> 2;            // 0..63
    const int lkc  = (tid & 3) * 8;       // half col 0,8,16,24
    const size_t gA = (size_t)(m0 + lrow) * K + lkc;
    const size_t gB = (size_t)(n0 + lrow) * K + lkc;
    const u32 sOff  = (u32)(lrow * GLD + lkc) * 2;
    const u32 sOff2 = sOff + 64 * GLD * 2;

    float acc[2][8][4];
    #pragma unroll
    for (int a = 0; a < 2; a++)
        #pragma unroll
        for (int b = 0; b < 8; b++)
            #pragma unroll
            for (int c = 0; c < 4; c++) acc[a][b][c] = 0.f;

    const u32 aOff = (u32)((wm * 32 + (lane & 15)) * GLD + (lane >> 4) * 8) * 2;
    const u32 bOff = (u32)((wn * 64 + (lane & 7) + ((lane >> 4) & 1) * 8) * GLD
                           + ((lane >> 3) & 1) * 8) * 2;

    const int nk = K / GBK;

    // prologue: stage 0
    {
        cp16(sAh0 + sOff,  Ah + gA);  cp16(sAh0 + sOff2, Ah + gA + (size_t)64 * K);
        cp16(sAl0 + sOff,  Al + gA);  cp16(sAl0 + sOff2, Al + gA + (size_t)64 * K);
        cp16(sBh0 + sOff,  Bh + gB);  cp16(sBh0 + sOff2, Bh + gB + (size_t)64 * K);
        asm volatile("cp.async.commit_group;\n");
    }

    for (int it = 0; it < nk; it++) {
        if (it + 1 < nk) {
            const int kk = (it + 1) * GBK;
            const u32 sb = (u32)(((it + 1) & 1) * GTILEB);
            cp16(sAh0 + sb + sOff,  Ah + gA + kk);
            cp16(sAh0 + sb + sOff2, Ah + gA + kk + (size_t)64 * K);
            cp16(sAl0 + sb + sOff,  Al + gA + kk);
            cp16(sAl0 + sb + sOff2, Al + gA + kk + (size_t)64 * K);
            cp16(sBh0 + sb + sOff,  Bh + gB + kk);
            cp16(sBh0 + sb + sOff2, Bh + gB + kk + (size_t)64 * K);
            asm volatile("cp.async.commit_group;\n");
            asm volatile("cp.async.wait_group 1;\n");
        } else {
            asm volatile("cp.async.wait_group 0;\n");
        }
        __syncthreads();

        const u32 sb = (u32)((it & 1) * GTILEB);
        #pragma unroll
        for (int ks = 0; ks < 2; ks++) {
            const u32 kb = sb + ks * 32;    // k16 step = 32 bytes
            u32 a_hi[2][4], a_lo[2][4], b_hi[4][4];
            #pragma unroll
            for (int mt = 0; mt < 2; mt++) {
                ldsm4(a_hi[mt], sAh0 + kb + aOff + mt * (16 * GLD * 2));
                ldsm4(a_lo[mt], sAl0 + kb + aOff + mt * (16 * GLD * 2));
            }
            #pragma unroll
            for (int np = 0; np < 4; np++)
                ldsm4(b_hi[np], sBh0 + kb + bOff + np * (16 * GLD * 2));
            #pragma unroll
            for (int mt = 0; mt < 2; mt++)
                #pragma unroll
                for (int nt = 0; nt < 8; nt++) {
                    const u32* bh = &b_hi[nt >> 1][(nt & 1) * 2];
                    mma16816(acc[mt][nt], a_hi[mt], bh);
                    mma16816(acc[mt][nt], a_lo[mt], bh);
                }
        }
        __syncthreads();
    }

    const int erow = m0 + wm * 32 + (lane >> 2);
    const int ecol = n0 + wn * 64 + (lane & 3) * 2;

    if (EPI == 0) {
        // plain fp32 output
        #pragma unroll
        for (int mt = 0; mt < 2; mt++)
            #pragma unroll
            for (int nt = 0; nt < 8; nt++) {
                int r = erow + mt * 16;
                int c = ecol + nt * 8;
                *(float2*)&C[(size_t)r * N + c] =
                    make_float2(acc[mt][nt][0], acc[mt][nt][1]);
                *(float2*)&C[(size_t)(r + 8) * N + c] =
                    make_float2(acc[mt][nt][2], acc[mt][nt][3]);
            }
    } else {
        // fused RoPE + fp16 hi/lo split into attention operand buffers.
        // Region uniform per CTA (boundaries 4096/5120 are 128-multiples).
        const int region = (n0 < DIM) ? 0 : ((n0 < DIM + KVDIM) ? 1 : 2);
        const float qscale = 0.08838834764831845f;   // 1/sqrt(128)
        float invf[8];
        #pragma unroll
        for (int nt = 0; nt < 8; nt++) {
            int c = ecol + nt * 8;
            invf[nt] = powf(10000.0f, -(float)(c & 127) / 128.0f);
        }
        #pragma unroll
        for (int mt = 0; mt < 2; mt++)
            #pragma unroll
            for (int nt = 0; nt < 8; nt++) {
                int c = ecol + nt * 8;
                #pragma unroll
                for (int hrow = 0; hrow < 2; hrow++) {
                    int r = erow + mt * 16 + hrow * 8;
                    float v0 = acc[mt][nt][hrow * 2];
                    float v1 = acc[mt][nt][hrow * 2 + 1];
                    if (region == 2) {
                        // V: plain fp16 convert (hi only; PV is 2-term)
                        size_t o = (size_t)r * KVDIM + (c - DIM - KVDIM);
                        *(__half2*)(vh + o) = __floats2half2_rn(v0, v1);
                    } else {
                        float sn, cs;
                        sincosf((float)r * invf[nt], &sn, &cs);
                        float o0 = v0 * cs - v1 * sn;
                        float o1 = v0 * sn + v1 * cs;
                        if (region == 0) { o0 *= qscale; o1 *= qscale; }
                        __half2 ll;
                        __half2 hh = split_pair(o0, o1, &ll);
                        if (region == 0) {
                            size_t o = (size_t)r * DIM + c;
                            *(__half2*)(qh + o) = hh;
                            *(__half2*)(ql + o) = ll;
                        } else {
                            size_t o = (size_t)r * KVDIM + (c - DIM);
                            *(__half2*)(kh + o) = hh;
                            *(__half2*)(kl + o) = ll;
                        }
                    }
                }
            }
    }
}

// ============================================================================
// Tensor-core flash attention (causal, GQA), fp16-split.
// S = QhKh + QlKh + QhKl (3-term);  O += PhVh + PlVh (2-term, V fp16).
// grid = (SEQ/64, NH), 128 threads; longest CTAs scheduled first.
// K and V are separate cp.async commit groups: S=QK^T overlaps the V stream.
// Epilogue writes the fp16 hi/lo split of O directly (feeds the wo GEMM).
// ============================================================================
#define LDB   136
#define ATILE (64 * LDB)
#define ASMEM (5 * ATILE * 2)    // Qh,Ql,Kh,Kl,Vh = 87040 B -> 2 CTAs/SM

__global__ __launch_bounds__(128) void attn_mma(
    const __half* __restrict__ Qh, const __half* __restrict__ Ql,
    const __half* __restrict__ Kh, const __half* __restrict__ Kl,
    const __half* __restrict__ Vh,
    __half* __restrict__ Oh, __half* __restrict__ Ol)
{
    extern __shared__ __half sma[];
    const u32 sQh = (u32)__cvta_generic_to_shared(sma);
    const u32 sQl = sQh + ATILE * 2;
    const u32 sKh = sQl + ATILE * 2;
    const u32 sKl = sKh + ATILE * 2;
    const u32 sVh = sKl + ATILE * 2;

    const int tid  = threadIdx.x;
    const int lane = tid & 31;
    const int warp = tid >> 5;
    const int qb   = gridDim.x - 1 - blockIdx.x;   // longest blocks first
    const int h    = blockIdx.y;
    const int kvh  = h >> 2;
    const int g    = lane >> 2;
    const int tig  = lane & 3;

    const int lrow  = tid >> 1;
    const int lhalf = (tid & 1) * 64;
    const u32 sOff  = (u32)(lrow * LDB + lhalf) * 2;

    {
        size_t qo = ((size_t)(qb * 64 + lrow) * NH + h) * HD + lhalf;
        #pragma unroll
        for (int c = 0; c < 8; c++) {
            cp16(sQh + sOff + c * 16, Qh + qo + c * 8);
            cp16(sQl + sOff + c * 16, Ql + qo + c * 8);
        }
        asm volatile("cp.async.commit_group;\n");
    }

    const u32 aO = (u32)((warp * 16 + (lane & 15)) * LDB) * 2 + (lane >> 4) * 16;
    const u32 bO = (u32)(((lane & 7) + ((lane >> 4) & 1) * 8) * LDB) * 2
                 + ((lane >> 3) & 1) * 16;
    const u32 vO = (u32)((lane & 15) * LDB) * 2 + (lane >> 4) * 16;

    float m[2] = {-1e30f, -1e30f}, l[2] = {0.f, 0.f};
    float acc[16][4];
    #pragma unroll
    for (int nt = 0; nt < 16; nt++)
        #pragma unroll
        for (int c = 0; c < 4; c++) acc[nt][c] = 0.f;

    for (int j = 0; j <= qb; j++) {
        __syncthreads();   // previous iteration's smem reads complete
        {
            size_t ko = ((size_t)(j * 64 + lrow) * NKV + kvh) * HD + lhalf;
            #pragma unroll
            for (int c = 0; c < 8; c++) {
                cp16(sKh + sOff + c * 16, Kh + ko + c * 8);
                cp16(sKl + sOff + c * 16, Kl + ko + c * 8);
            }
            asm volatile("cp.async.commit_group;\n");   // group: K
            #pragma unroll
            for (int c = 0; c < 8; c++)
                cp16(sVh + sOff + c * 16, Vh + ko + c * 8);
            asm volatile("cp.async.commit_group;\n");   // group: V
            asm volatile("cp.async.wait_group 1;\n");   // K (and Q) ready
        }
        __syncthreads();

        float sv[8][4];
        #pragma unroll
        for (int nt = 0; nt < 8; nt++)
            #pragma unroll
            for (int c = 0; c < 4; c++) sv[nt][c] = 0.f;

        #pragma unroll
        for (int ks = 0; ks < 8; ks++) {
            const u32 kb = ks * 32;
            u32 ah[4], al[4];
            ldsm4(ah, sQh + aO + kb);
            ldsm4(al, sQl + aO + kb);
            #pragma unroll
            for (int np = 0; np < 4; np++) {
                u32 bh[4], bl[4];
                ldsm4(bh, sKh + bO + np * (16 * LDB * 2) + kb);
                ldsm4(bl, sKl + bO + np * (16 * LDB * 2) + kb);
                mma16816(sv[2 * np],     ah, &bh[0]);
                mma16816(sv[2 * np],     al, &bh[0]);
                mma16816(sv[2 * np],     ah, &bl[0]);
                mma16816(sv[2 * np + 1], ah, &bh[2]);
                mma16816(sv[2 * np + 1], al, &bh[2]);
                mma16816(sv[2 * np + 1], ah, &bl[2]);
            }
        }

        if (j == qb) {
            #pragma unroll
            for (int nt = 0; nt < 8; nt++)
                #pragma unroll
                for (int c = 0; c < 4; c++) {
                    int col = nt * 8 + tig * 2 + (c & 1);
                    int row = warp * 16 + g + (c >> 1) * 8;
                    if (col > row) sv[nt][c] = -1e30f;
                }
        }

        #pragma unroll
        for (int half = 0; half < 2; half++) {
            float rm = -1e30f;
            #pragma unroll
            for (int nt = 0; nt < 8; nt++)
                rm = fmaxf(rm, fmaxf(sv[nt][half * 2], sv[nt][half * 2 + 1]));
            rm = fmaxf(rm, __shfl_xor_sync(0xffffffffu, rm, 1));
            rm = fmaxf(rm, __shfl_xor_sync(0xffffffffu, rm, 2));
            float mn   = fmaxf(m[half], rm);
            float corr = __expf(m[half] - mn);
            float rs = 0.f;
            #pragma unroll
            for (int nt = 0; nt < 8; nt++) {
                float p0 = __expf(sv[nt][half * 2]     - mn);
                float p1 = __expf(sv[nt][half * 2 + 1] - mn);
                sv[nt][half * 2]     = p0;
                sv[nt][half * 2 + 1] = p1;
                rs += p0 + p1;
            }
            rs += __shfl_xor_sync(0xffffffffu, rs, 1);
            rs += __shfl_xor_sync(0xffffffffu, rs, 2);
            l[half] = l[half] * corr + rs;
            m[half] = mn;
            #pragma unroll
            for (int nt = 0; nt < 16; nt++) {
                acc[nt][half * 2]     *= corr;
                acc[nt][half * 2 + 1] *= corr;
            }
        }

        // V stream must be fully landed (all threads) before P@V
        asm volatile("cp.async.wait_group 0;\n");
        __syncthreads();

        #pragma unroll
        for (int ks = 0; ks < 4; ks++) {
            u32 pa_h[4], pa_l[4];
            #pragma unroll
            for (int t = 0; t < 2; t++) {
                __half2 l01, l23;
                __half2 h01 = split_pair(sv[2 * ks + t][0], sv[2 * ks + t][1], &l01);
                __half2 h23 = split_pair(sv[2 * ks + t][2], sv[2 * ks + t][3], &l23);
                pa_h[2 * t]     = *(u32*)&h01;
                pa_h[2 * t + 1] = *(u32*)&h23;
                pa_l[2 * t]     = *(u32*)&l01;
                pa_l[2 * t + 1] = *(u32*)&l23;
            }
            const u32 kb = (u32)(ks * 16 * LDB) * 2;
            #pragma unroll
            for (int np = 0; np < 8; np++) {
                u32 vh[4];
                ldsm4t(vh, sVh + vO + kb + np * 32);
                mma16816(acc[2 * np],     pa_h, &vh[0]);
                mma16816(acc[2 * np],     pa_l, &vh[0]);
                mma16816(acc[2 * np + 1], pa_h, &vh[2]);
                mma16816(acc[2 * np + 1], pa_l, &vh[2]);
            }
        }
    }

    // ---- epilogue: normalize + fp16 hi/lo split, write directly ----
    #pragma unroll
    for (int half = 0; half < 2; half++) {
        float inv = 1.0f / l[half];
        int row = qb * 64 + warp * 16 + g + half * 8;
        size_t base = (size_t)row * DIM + h * HD;
        #pragma unroll
        for (int nt = 0; nt < 16; nt++) {
            int col = nt * 8 + tig * 2;
            __half2 ll;
            __half2 hh = split_pair(acc[nt][half * 2] * inv,
                                    acc[nt][half * 2 + 1] * inv, &ll);
            *(__half2*)(Oh + base + col) = hh;
            *(__half2*)(Ol + base + col) = ll;
        }
    }
}

// ============================================================================
// kernel_launch
// ============================================================================
extern "C" void kernel_launch(void* const* d_in, const int* in_sizes, int n_in,
                              void* d_out, int out_size)
{
    const float* x  = (const float*)d_in[0];
    const float* wq = (const float*)d_in[1];
    const float* wk = (const float*)d_in[2];
    const float* wv = (const float*)d_in[3];
    const float* wo = (const float*)d_in[4];
    float* out = (float*)d_out;

    __half *xh, *xl, *wh, *woh, *ah, *al;
    __half *qbh, *qbl, *kbh, *kbl, *vbh;
    cudaGetSymbolAddress((void**)&xh,  g_xh);  cudaGetSymbolAddress((void**)&xl,  g_xl);
    cudaGetSymbolAddress((void**)&wh,  g_wh);
    cudaGetSymbolAddress((void**)&woh, g_woh);
    cudaGetSymbolAddress((void**)&ah,  g_ah);  cudaGetSymbolAddress((void**)&al,  g_al);
    cudaGetSymbolAddress((void**)&qbh, g_qbh); cudaGetSymbolAddress((void**)&qbl, g_qbl);
    cudaGetSymbolAddress((void**)&kbh, g_kbh); cudaGetSymbolAddress((void**)&kbl, g_kbl);
    cudaGetSymbolAddress((void**)&vbh, g_vbh);

    cudaFuncSetAttribute(gemm_fp16x2<1>,
                         cudaFuncAttributeMaxDynamicSharedMemorySize, GSMEM);
    cudaFuncSetAttribute(gemm_fp16x2<0>,
                         cudaFuncAttributeMaxDynamicSharedMemorySize, GSMEM);
    cudaFuncSetAttribute(attn_mma,
                         cudaFuncAttributeMaxDynamicSharedMemorySize, ASMEM);

    // 1) split x; transpose weights (hi-only; weights are fp16-quantized)
    split_kernel<<<(SEQ * DIM / 4 + 255) / 256, 256>>>(x, xh, xl, SEQ * DIM / 4);
    transpose_half_kernel<<<dim3(DIM   / 32, DIM / 32), dim3(32, 8)>>>(
        wq, wh, DIM, DIM);
    transpose_half_kernel<<<dim3(KVDIM / 32, DIM / 32), dim3(32, 8)>>>(
        wk, wh + (size_t)DIM * DIM, DIM, KVDIM);
    transpose_half_kernel<<<dim3(KVDIM / 32, DIM / 32), dim3(32, 8)>>>(
        wv, wh + (size_t)(DIM + KVDIM) * DIM, DIM, KVDIM);
    transpose_half_kernel<<<dim3(DIM   / 32, DIM / 32), dim3(32, 8)>>>(
        wo, woh, DIM, DIM);

    // 2) fused QKV projection (2-term); epilogue applies RoPE + split in-place
    gemm_fp16x2<1><<<dim3(QKVN / 128, SEQ / 128), 256, GSMEM>>>(
        xh, xl, wh, nullptr, SEQ, QKVN, DIM,
        qbh, qbl, kbh, kbl, vbh);

    // 3) tensor-core attention (epilogue writes split O directly)
    attn_mma<<<dim3(SEQ / 64, NH), 128, ASMEM>>>(
        qbh, qbl, kbh, kbl, vbh, ah, al);

    // 4) output projection (2-term: wo fp16-quantized)
    gemm_fp16x2<0><<<dim3(DIM / 128, SEQ / 128), 256, GSMEM>>>(
        ah, al, woh, out, SEQ, DIM, DIM,
        nullptr, nullptr, nullptr, nullptr, nullptr);
}

// round 17
// speedup vs baseline: 1.8371x; 1.0420x over previous
#include <cuda_runtime.h>
#include <cuda_fp16.h>
#include <math.h>

// Problem constants
#define SEQ   2048
#define DIM   4096
#define NH    32
#define NKV   8
#define HD    128
#define KVDIM (NKV * HD)     // 1024
#define QKVN  (DIM + 2 * KVDIM)  // 6144

typedef unsigned int u32;

// -------- scratch (device globals; no runtime allocation allowed) --------
__device__ __half g_xh[SEQ * DIM],   g_xl[SEQ * DIM];  // split x
__device__ __half g_wh[QKVN * DIM];                    // wq|wk|wv fp16 [N][K]
__device__ __half g_woh[DIM * DIM];                    // wo fp16 [N][K]
__device__ __half g_ah[SEQ * DIM],   g_al[SEQ * DIM];  // attention out (split)
__device__ __half g_qbh[SEQ * DIM],   g_qbl[SEQ * DIM];
__device__ __half g_kbh[SEQ * KVDIM], g_kbl[SEQ * KVDIM];
__device__ __half g_vbh[SEQ * KVDIM];                  // V hi only (2-term PV)

// ============================================================================
// PTX primitives (legacy tensor path — tcgen05 not supported by this build)
// ============================================================================
__device__ __forceinline__ void ldsm4(u32* r, u32 addr) {
    asm volatile("ldmatrix.sync.aligned.m8n8.x4.shared.b16 {%0,%1,%2,%3}, [%4];\n"
        : "=r"(r[0]), "=r"(r[1]), "=r"(r[2]), "=r"(r[3]) : "r"(addr));
}
__device__ __forceinline__ void ldsm4t(u32* r, u32 addr) {
    asm volatile("ldmatrix.sync.aligned.m8n8.x4.trans.shared.b16 {%0,%1,%2,%3}, [%4];\n"
        : "=r"(r[0]), "=r"(r[1]), "=r"(r[2]), "=r"(r[3]) : "r"(addr));
}
__device__ __forceinline__ void mma16816(float* c, const u32* a, const u32* b) {
    asm volatile("mma.sync.aligned.m16n8k16.row.col.f32.f16.f16.f32 "
        "{%0,%1,%2,%3}, {%4,%5,%6,%7}, {%8,%9}, {%0,%1,%2,%3};\n"
        : "+f"(c[0]), "+f"(c[1]), "+f"(c[2]), "+f"(c[3])
        : "r"(a[0]), "r"(a[1]), "r"(a[2]), "r"(a[3]), "r"(b[0]), "r"(b[1]));
}
__device__ __forceinline__ void cp16(u32 dst, const void* src) {
    asm volatile("cp.async.cg.shared.global [%0], [%1], 16;\n" :: "r"(dst), "l"(src));
}
__device__ __forceinline__ __half2 split_pair(float v0, float v1, __half2* lo) {
    __half2 hh = __floats2half2_rn(v0, v1);
    *lo = __floats2half2_rn(v0 - __half2float(__low2half(hh)),
                            v1 - __half2float(__high2half(hh)));
    return hh;
}

// ============================================================================
// Split fp32 -> fp16 hi + fp16 lo(residual). Vectorized x4.
// ============================================================================
__global__ void split_kernel(const float* __restrict__ in,
                             __half* __restrict__ hi,
                             __half* __restrict__ lo, int n4)
{
    int i = blockIdx.x * blockDim.x + threadIdx.x;
    if (i >= n4) return;
    float4 v = ((const float4*)in)[i];
    __half2 l01, l23;
    __half2 h01 = split_pair(v.x, v.y, &l01);
    __half2 h23 = split_pair(v.z, v.w, &l23);
    ((__half2*)hi)[2 * i]     = h01;
    ((__half2*)hi)[2 * i + 1] = h23;
    ((__half2*)lo)[2 * i]     = l01;
    ((__half2*)lo)[2 * i + 1] = l23;
}

// ============================================================================
// Transpose (fp32 [K][N] -> fp16 [N][K], hi only — weights are fp16-quantized).
// ============================================================================
__global__ void transpose_half_kernel(const float* __restrict__ in,
                                      __half* __restrict__ hi,
                                      int K, int N)
{
    __shared__ float t[32][33];
    int n0 = blockIdx.x * 32, k0 = blockIdx.y * 32;
    int tx = threadIdx.x, ty = threadIdx.y;   // (32, 8)
    #pragma unroll
    for (int i = 0; i < 4; i++)
        t[ty + i * 8][tx] = in[(size_t)(k0 + ty + i * 8) * N + n0 + tx];
    __syncthreads();
    #pragma unroll
    for (int i = 0; i < 4; i++) {
        float v = t[tx][ty + i * 8];
        hi[(size_t)(n0 + ty + i * 8) * K + k0 + tx] = __float2half_rn(v);
    }
}

// ============================================================================
// fp16-split tensor-core GEMM: C[M,N] fp32 = A @ B^T  (2-term: AhBh + AlBh).
// A: hi/lo fp16 [M][K];  B: fp16 [N][K] (K-major).
// 128x128x32 tiles, 256 threads, 3-stage cp.async pipeline:
// one __syncthreads per iteration; fills issue after the barrier and fully
// overlap compute (2 tiles in flight).  92,160 B smem -> 2 CTAs/SM.
// EPI=1: fused RoPE + fp16 hi/lo split into Q/K/V attention operand buffers.
// ============================================================================
#define GBK    32
#define GLD    40                 // padded row stride in halfs
#define GTILE  (128 * GLD)
#define GTILEB (GTILE * 2)        // 10240 bytes per tile
#define GSTAGE (3 * GTILEB)       // Ah,Al,Bh = 30720 bytes per stage
#define GSMEM  (3 * GSTAGE)       // 3 stages = 92160 B

template<int EPI>
__global__ __launch_bounds__(256) void gemm_fp16x2(
    const __half* __restrict__ Ah, const __half* __restrict__ Al,
    const __half* __restrict__ Bh,
    float* __restrict__ C, int M, int N, int K,
    __half* __restrict__ qh, __half* __restrict__ ql,
    __half* __restrict__ kh, __half* __restrict__ kl,
    __half* __restrict__ vh)
{
    extern __shared__ __half smg[];
    const u32 smb = (u32)__cvta_generic_to_shared(smg);

    const int tid  = threadIdx.x;
    const int lane = tid & 31;
    const int warp = tid >> 5;
    const int wm   = warp & 3;    // 0..3 -> 32-row slab
    const int wn   = warp >> 2;   // 0..1 -> 64-col slab
    const int m0   = blockIdx.y * 128;
    const int n0   = blockIdx.x * 128;

    // loader: 2 x 16B per tile per thread (rows r, r+64)
    const int lrow = tid >> 2;            // 0..63
    const int lkc  = (tid & 3) * 8;       // half col 0,8,16,24
    const size_t gA = (size_t)(m0 + lrow) * K + lkc;
    const size_t gB = (size_t)(n0 + lrow) * K + lkc;
    const u32 sOff  = (u32)(lrow * GLD + lkc) * 2;
    const u32 sOff2 = sOff + 64 * GLD * 2;

    float acc[2][8][4];
    #pragma unroll
    for (int a = 0; a < 2; a++)
        #pragma unroll
        for (int b = 0; b < 8; b++)
            #pragma unroll
            for (int c = 0; c < 4; c++) acc[a][b][c] = 0.f;

    const u32 aOff = (u32)((wm * 32 + (lane & 15)) * GLD + (lane >> 4) * 8) * 2;
    const u32 bOff = (u32)((wn * 64 + (lane & 7) + ((lane >> 4) & 1) * 8) * GLD
                           + ((lane >> 3) & 1) * 8) * 2;

    const int nk = K / GBK;

    auto fill = [&](int s, int kt) {
        const u32 st = smb + (u32)s * GSTAGE;
        const int kk = kt * GBK;
        cp16(st + sOff,  Ah + gA + kk);
        cp16(st + sOff2, Ah + gA + kk + (size_t)64 * K);
        cp16(st + GTILEB + sOff,  Al + gA + kk);
        cp16(st + GTILEB + sOff2, Al + gA + kk + (size_t)64 * K);
        cp16(st + 2 * GTILEB + sOff,  Bh + gB + kk);
        cp16(st + 2 * GTILEB + sOff2, Bh + gB + kk + (size_t)64 * K);
        asm volatile("cp.async.commit_group;\n");
    };

    fill(0, 0);
    if (nk > 1) fill(1, 1);

    for (int it = 0; it < nk; it++) {
        if (it + 1 < nk) asm volatile("cp.async.wait_group 1;\n" ::: "memory");
        else             asm volatile("cp.async.wait_group 0;\n" ::: "memory");
        __syncthreads();
        if (it + 2 < nk) fill((it + 2) % 3, it + 2);   // overlaps compute below

        const u32 st = smb + (u32)(it % 3) * GSTAGE;
        #pragma unroll
        for (int ks = 0; ks < 2; ks++) {
            const u32 kb = ks * 32;    // k16 step = 32 bytes
            u32 a_hi[2][4], a_lo[2][4], b_hi[4][4];
            #pragma unroll
            for (int mt = 0; mt < 2; mt++) {
                ldsm4(a_hi[mt], st + kb + aOff + mt * (16 * GLD * 2));
                ldsm4(a_lo[mt], st + GTILEB + kb + aOff + mt * (16 * GLD * 2));
            }
            #pragma unroll
            for (int np = 0; np < 4; np++)
                ldsm4(b_hi[np], st + 2 * GTILEB + kb + bOff + np * (16 * GLD * 2));
            #pragma unroll
            for (int mt = 0; mt < 2; mt++)
                #pragma unroll
                for (int nt = 0; nt < 8; nt++) {
                    const u32* bh = &b_hi[nt >> 1][(nt & 1) * 2];
                    mma16816(acc[mt][nt], a_hi[mt], bh);
                    mma16816(acc[mt][nt], a_lo[mt], bh);
                }
        }
    }

    const int erow = m0 + wm * 32 + (lane >> 2);
    const int ecol = n0 + wn * 64 + (lane & 3) * 2;

    if (EPI == 0) {
        #pragma unroll
        for (int mt = 0; mt < 2; mt++)
            #pragma unroll
            for (int nt = 0; nt < 8; nt++) {
                int r = erow + mt * 16;
                int c = ecol + nt * 8;
                *(float2*)&C[(size_t)r * N + c] =
                    make_float2(acc[mt][nt][0], acc[mt][nt][1]);
                *(float2*)&C[(size_t)(r + 8) * N + c] =
                    make_float2(acc[mt][nt][2], acc[mt][nt][3]);
            }
    } else {
        // fused RoPE + fp16 hi/lo split into attention operand buffers.
        const int region = (n0 < DIM) ? 0 : ((n0 < DIM + KVDIM) ? 1 : 2);
        const float qscale = 0.08838834764831845f;   // 1/sqrt(128)
        float invf[8];
        #pragma unroll
        for (int nt = 0; nt < 8; nt++) {
            int c = ecol + nt * 8;
            invf[nt] = powf(10000.0f, -(float)(c & 127) / 128.0f);
        }
        #pragma unroll
        for (int mt = 0; mt < 2; mt++)
            #pragma unroll
            for (int nt = 0; nt < 8; nt++) {
                int c = ecol + nt * 8;
                #pragma unroll
                for (int hrow = 0; hrow < 2; hrow++) {
                    int r = erow + mt * 16 + hrow * 8;
                    float v0 = acc[mt][nt][hrow * 2];
                    float v1 = acc[mt][nt][hrow * 2 + 1];
                    if (region == 2) {
                        size_t o = (size_t)r * KVDIM + (c - DIM - KVDIM);
                        *(__half2*)(vh + o) = __floats2half2_rn(v0, v1);
                    } else {
                        float sn, cs;
                        sincosf((float)r * invf[nt], &sn, &cs);
                        float o0 = v0 * cs - v1 * sn;
                        float o1 = v0 * sn + v1 * cs;
                        if (region == 0) { o0 *= qscale; o1 *= qscale; }
                        __half2 ll;
                        __half2 hh = split_pair(o0, o1, &ll);
                        if (region == 0) {
                            size_t o = (size_t)r * DIM + c;
                            *(__half2*)(qh + o) = hh;
                            *(__half2*)(ql + o) = ll;
                        } else {
                            size_t o = (size_t)r * KVDIM + (c - DIM);
                            *(__half2*)(kh + o) = hh;
                            *(__half2*)(kl + o) = ll;
                        }
                    }
                }
            }
    }
}

// ============================================================================
// Tensor-core flash attention (causal, GQA), fp16-split.
// S = QhKh + QlKh + QhKl (3-term);  O += PhVh + PlVh (2-term, V fp16).
// Q fragments held in REGISTERS (loaded once); K/V double-buffered in smem,
// next tile streams via cp.async during the current tile's compute.
// grid = (SEQ/64, NH), 128 threads; longest CTAs scheduled first.
// ============================================================================
#define LDB    136
#define ATILEB (64 * LDB * 2)      // 17408 bytes per tile
#define ASTAGE (3 * ATILEB)        // Kh,Kl,Vh = 52224 bytes per stage
#define ASMEM  (2 * ASTAGE)        // 104448 B -> 2 CTAs/SM

__global__ __launch_bounds__(128) void attn_mma(
    const __half* __restrict__ Qh, const __half* __restrict__ Ql,
    const __half* __restrict__ Kh, const __half* __restrict__ Kl,
    const __half* __restrict__ Vh,
    __half* __restrict__ Oh, __half* __restrict__ Ol)
{
    extern __shared__ __half sma[];
    const u32 smb = (u32)__cvta_generic_to_shared(sma);

    const int tid  = threadIdx.x;
    const int lane = tid & 31;
    const int warp = tid >> 5;
    const int qb   = gridDim.x - 1 - blockIdx.x;   // longest blocks first
    const int h    = blockIdx.y;
    const int kvh  = h >> 2;
    const int g    = lane >> 2;
    const int tig  = lane & 3;

    const int lrow  = tid >> 1;
    const int lhalf = (tid & 1) * 64;
    const u32 sOff  = (u32)(lrow * LDB + lhalf) * 2;

    const u32 aO = (u32)((warp * 16 + (lane & 15)) * LDB) * 2 + (lane >> 4) * 16;
    const u32 bO = (u32)(((lane & 7) + ((lane >> 4) & 1) * 8) * LDB) * 2
                 + ((lane >> 3) & 1) * 16;
    const u32 vO = (u32)((lane & 15) * LDB) * 2 + (lane >> 4) * 16;

    // ---- load Q tile into stage-0 smem, then hoist fragments to registers ----
    {
        size_t qo = ((size_t)(qb * 64 + lrow) * NH + h) * HD + lhalf;
        #pragma unroll
        for (int c = 0; c < 8; c++) {
            cp16(smb + sOff + c * 16,          Qh + qo + c * 8);
            cp16(smb + ATILEB + sOff + c * 16, Ql + qo + c * 8);
        }
        asm volatile("cp.async.commit_group;\n");
        asm volatile("cp.async.wait_group 0;\n");
    }
    __syncthreads();
    u32 qfh[8][4], qfl[8][4];
    #pragma unroll
    for (int ks = 0; ks < 8; ks++) {
        ldsm4(qfh[ks], smb + aO + ks * 32);
        ldsm4(qfl[ks], smb + ATILEB + aO + ks * 32);
    }
    __syncthreads();   // all warps done reading Q before K/V fills overwrite

    auto fillkv = [&](int s, int j) {
        const u32 st = smb + (u32)s * ASTAGE;
        size_t ko = ((size_t)(j * 64 + lrow) * NKV + kvh) * HD + lhalf;
        #pragma unroll
        for (int c = 0; c < 8; c++) {
            cp16(st + sOff + c * 16,              Kh + ko + c * 8);
            cp16(st + ATILEB + sOff + c * 16,     Kl + ko + c * 8);
            cp16(st + 2 * ATILEB + sOff + c * 16, Vh + ko + c * 8);
        }
        asm volatile("cp.async.commit_group;\n");
    };

    float m[2] = {-1e30f, -1e30f}, l[2] = {0.f, 0.f};
    float acc[16][4];
    #pragma unroll
    for (int nt = 0; nt < 16; nt++)
        #pragma unroll
        for (int c = 0; c < 4; c++) acc[nt][c] = 0.f;

    fillkv(0, 0);

    for (int j = 0; j <= qb; j++) {
        const int s = j & 1;
        // prefetch next tile into the other stage (its last reader finished
        // at the trailing barrier of iteration j-1); overlaps compute below
        if (j + 1 <= qb) {
            fillkv(1 - s, j + 1);
            asm volatile("cp.async.wait_group 1;\n" ::: "memory");
        } else {
            asm volatile("cp.async.wait_group 0;\n" ::: "memory");
        }
        __syncthreads();

        const u32 st = smb + (u32)s * ASTAGE;

        float sv[8][4];
        #pragma unroll
        for (int nt = 0; nt < 8; nt++)
            #pragma unroll
            for (int c = 0; c < 4; c++) sv[nt][c] = 0.f;

        #pragma unroll
        for (int ks = 0; ks < 8; ks++) {
            const u32 kb = ks * 32;
            #pragma unroll
            for (int np = 0; np < 4; np++) {
                u32 bh[4], bl[4];
                ldsm4(bh, st + bO + np * (16 * LDB * 2) + kb);
                ldsm4(bl, st + ATILEB + bO + np * (16 * LDB * 2) + kb);
                mma16816(sv[2 * np],     qfh[ks], &bh[0]);
                mma16816(sv[2 * np],     qfl[ks], &bh[0]);
                mma16816(sv[2 * np],     qfh[ks], &bl[0]);
                mma16816(sv[2 * np + 1], qfh[ks], &bh[2]);
                mma16816(sv[2 * np + 1], qfl[ks], &bh[2]);
                mma16816(sv[2 * np + 1], qfh[ks], &bl[2]);
            }
        }

        if (j == qb) {
            #pragma unroll
            for (int nt = 0; nt < 8; nt++)
                #pragma unroll
                for (int c = 0; c < 4; c++) {
                    int col = nt * 8 + tig * 2 + (c & 1);
                    int row = warp * 16 + g + (c >> 1) * 8;
                    if (col > row) sv[nt][c] = -1e30f;
                }
        }

        #pragma unroll
        for (int half = 0; half < 2; half++) {
            float rm = -1e30f;
            #pragma unroll
            for (int nt = 0; nt < 8; nt++)
                rm = fmaxf(rm, fmaxf(sv[nt][half * 2], sv[nt][half * 2 + 1]));
            rm = fmaxf(rm, __shfl_xor_sync(0xffffffffu, rm, 1));
            rm = fmaxf(rm, __shfl_xor_sync(0xffffffffu, rm, 2));
            float mn   = fmaxf(m[half], rm);
            float corr = __expf(m[half] - mn);
            float rs = 0.f;
            #pragma unroll
            for (int nt = 0; nt < 8; nt++) {
                float p0 = __expf(sv[nt][half * 2]     - mn);
                float p1 = __expf(sv[nt][half * 2 + 1] - mn);
                sv[nt][half * 2]     = p0;
                sv[nt][half * 2 + 1] = p1;
                rs += p0 + p1;
            }
            rs += __shfl_xor_sync(0xffffffffu, rs, 1);
            rs += __shfl_xor_sync(0xffffffffu, rs, 2);
            l[half] = l[half] * corr + rs;
            m[half] = mn;
            #pragma unroll
            for (int nt = 0; nt < 16; nt++) {
                acc[nt][half * 2]     *= corr;
                acc[nt][half * 2 + 1] *= corr;
            }
        }

        #pragma unroll
        for (int ks = 0; ks < 4; ks++) {
            u32 pa_h[4], pa_l[4];
            #pragma unroll
            for (int t = 0; t < 2; t++) {
                __half2 l01, l23;
                __half2 h01 = split_pair(sv[2 * ks + t][0], sv[2 * ks + t][1], &l01);
                __half2 h23 = split_pair(sv[2 * ks + t][2], sv[2 * ks + t][3], &l23);
                pa_h[2 * t]     = *(u32*)&h01;
                pa_h[2 * t + 1] = *(u32*)&h23;
                pa_l[2 * t]     = *(u32*)&l01;
                pa_l[2 * t + 1] = *(u32*)&l23;
            }
            const u32 kb = (u32)(ks * 16 * LDB) * 2;
            #pragma unroll
            for (int np = 0; np < 8; np++) {
                u32 vh[4];
                ldsm4t(vh, st + 2 * ATILEB + vO + kb + np * 32);
                mma16816(acc[2 * np],     pa_h, &vh[0]);
                mma16816(acc[2 * np],     pa_l, &vh[0]);
                mma16816(acc[2 * np + 1], pa_h, &vh[2]);
                mma16816(acc[2 * np + 1], pa_l, &vh[2]);
            }
        }
        __syncthreads();   // all warps done with stage s before it refills
    }

    // ---- epilogue: normalize + fp16 hi/lo split, write directly ----
    #pragma unroll
    for (int half = 0; half < 2; half++) {
        float inv = 1.0f / l[half];
        int row = qb * 64 + warp * 16 + g + half * 8;
        size_t base = (size_t)row * DIM + h * HD;
        #pragma unroll
        for (int nt = 0; nt < 16; nt++) {
            int col = nt * 8 + tig * 2;
            __half2 ll;
            __half2 hh = split_pair(acc[nt][half * 2] * inv,
                                    acc[nt][half * 2 + 1] * inv, &ll);
            *(__half2*)(Oh + base + col) = hh;
            *(__half2*)(Ol + base + col) = ll;
        }
    }
}

// ============================================================================
// kernel_launch
// ============================================================================
extern "C" void kernel_launch(void* const* d_in, const int* in_sizes, int n_in,
                              void* d_out, int out_size)
{
    const float* x  = (const float*)d_in[0];
    const float* wq = (const float*)d_in[1];
    const float* wk = (const float*)d_in[2];
    const float* wv = (const float*)d_in[3];
    const float* wo = (const float*)d_in[4];
    float* out = (float*)d_out;

    __half *xh, *xl, *wh, *woh, *ah, *al;
    __half *qbh, *qbl, *kbh, *kbl, *vbh;
    cudaGetSymbolAddress((void**)&xh,  g_xh);  cudaGetSymbolAddress((void**)&xl,  g_xl);
    cudaGetSymbolAddress((void**)&wh,  g_wh);
    cudaGetSymbolAddress((void**)&woh, g_woh);
    cudaGetSymbolAddress((void**)&ah,  g_ah);  cudaGetSymbolAddress((void**)&al,  g_al);
    cudaGetSymbolAddress((void**)&qbh, g_qbh); cudaGetSymbolAddress((void**)&qbl, g_qbl);
    cudaGetSymbolAddress((void**)&kbh, g_kbh); cudaGetSymbolAddress((void**)&kbl, g_kbl);
    cudaGetSymbolAddress((void**)&vbh, g_vbh);

    cudaFuncSetAttribute(gemm_fp16x2<1>,
                         cudaFuncAttributeMaxDynamicSharedMemorySize, GSMEM);
    cudaFuncSetAttribute(gemm_fp16x2<0>,
                         cudaFuncAttributeMaxDynamicSharedMemorySize, GSMEM);
    cudaFuncSetAttribute(attn_mma,
                         cudaFuncAttributeMaxDynamicSharedMemorySize, ASMEM);

    // 1) split x; transpose weights (hi-only; weights are fp16-quantized)
    split_kernel<<<(SEQ * DIM / 4 + 255) / 256, 256>>>(x, xh, xl, SEQ * DIM / 4);
    transpose_half_kernel<<<dim3(DIM   / 32, DIM / 32), dim3(32, 8)>>>(
        wq, wh, DIM, DIM);
    transpose_half_kernel<<<dim3(KVDIM / 32, DIM / 32), dim3(32, 8)>>>(
        wk, wh + (size_t)DIM * DIM, DIM, KVDIM);
    transpose_half_kernel<<<dim3(KVDIM / 32, DIM / 32), dim3(32, 8)>>>(
        wv, wh + (size_t)(DIM + KVDIM) * DIM, DIM, KVDIM);
    transpose_half_kernel<<<dim3(DIM   / 32, DIM / 32), dim3(32, 8)>>>(
        wo, woh, DIM, DIM);

    // 2) fused QKV projection (2-term); epilogue applies RoPE + split in-place
    gemm_fp16x2<1><<<dim3(QKVN / 128, SEQ / 128), 256, GSMEM>>>(
        xh, xl, wh, nullptr, SEQ, QKVN, DIM,
        qbh, qbl, kbh, kbl, vbh);

    // 3) tensor-core attention (Q in registers, K/V double-buffered)
    attn_mma<<<dim3(SEQ / 64, NH), 128, ASMEM>>>(
        qbh, qbl, kbh, kbl, vbh, ah, al);

    // 4) output projection (2-term: wo fp16-quantized)
    gemm_fp16x2<0><<<dim3(DIM / 128, SEQ / 128), 256, GSMEM>>>(
        ah, al, woh, out, SEQ, DIM, DIM,
        nullptr, nullptr, nullptr, nullptr, nullptr);
}